// round 2
// baseline (speedup 1.0000x reference)
#include <cuda_runtime.h>

// Problem constants
#define BB  4
#define NN  2048
#define DD  256
#define HH  8
#define DKK 32
#define INV_SCALE 0.17677669529663687f   // 1/sqrt(32)

// Scratch (device globals; allocation-free per harness rules)
__device__ float g_Q [BB*HH*NN*DKK];   // [b][h][n][dk]
__device__ float g_K [BB*HH*NN*DKK];
__device__ float g_V [BB*HH*NN*DKK];
__device__ float g_AO[BB*NN*DD];       // [b][n][h*DK+dk] == [row][d]

// ---------------------------------------------------------------------------
// Kernel 1: QKV projection.  Y = X @ W^T, written in head-split layout.
// grid = (128, 4, 3), block = 256. 64x64 tile, BK=32, 4x4 per thread.
// ---------------------------------------------------------------------------
__global__ __launch_bounds__(256) void qkv_kernel(
    const float* __restrict__ X,
    const float* __restrict__ Wq,
    const float* __restrict__ Wk,
    const float* __restrict__ Wv)
{
    __shared__ float Xs[64][33];
    __shared__ float Ws[64][33];

    const float* W = (blockIdx.z == 0) ? Wq : (blockIdx.z == 1) ? Wk : Wv;
    float*       Y = (blockIdx.z == 0) ? g_Q : (blockIdx.z == 1) ? g_K : g_V;

    const int row0 = blockIdx.x * 64;
    const int col0 = blockIdx.y * 64;
    const int t  = threadIdx.x;
    const int ti = t >> 4, tj = t & 15;
    const int i0 = ti * 4, j0 = tj * 4;

    float acc[4][4];
#pragma unroll
    for (int r = 0; r < 4; r++)
#pragma unroll
        for (int c = 0; c < 4; c++) acc[r][c] = 0.f;

    for (int k0 = 0; k0 < DD; k0 += 32) {
        __syncthreads();
        for (int idx = t; idx < 64 * 32; idx += 256) {
            int r = idx >> 5, k = idx & 31;
            Xs[r][k] = X[(row0 + r) * DD + k0 + k];
            Ws[r][k] = W[(col0 + r) * DD + k0 + k];
        }
        __syncthreads();
#pragma unroll
        for (int k = 0; k < 32; k++) {
            float a0 = Xs[i0+0][k], a1 = Xs[i0+1][k], a2 = Xs[i0+2][k], a3 = Xs[i0+3][k];
            float b0 = Ws[j0+0][k], b1 = Ws[j0+1][k], b2 = Ws[j0+2][k], b3 = Ws[j0+3][k];
            acc[0][0] = fmaf(a0,b0,acc[0][0]); acc[0][1] = fmaf(a0,b1,acc[0][1]);
            acc[0][2] = fmaf(a0,b2,acc[0][2]); acc[0][3] = fmaf(a0,b3,acc[0][3]);
            acc[1][0] = fmaf(a1,b0,acc[1][0]); acc[1][1] = fmaf(a1,b1,acc[1][1]);
            acc[1][2] = fmaf(a1,b2,acc[1][2]); acc[1][3] = fmaf(a1,b3,acc[1][3]);
            acc[2][0] = fmaf(a2,b0,acc[2][0]); acc[2][1] = fmaf(a2,b1,acc[2][1]);
            acc[2][2] = fmaf(a2,b2,acc[2][2]); acc[2][3] = fmaf(a2,b3,acc[2][3]);
            acc[3][0] = fmaf(a3,b0,acc[3][0]); acc[3][1] = fmaf(a3,b1,acc[3][1]);
            acc[3][2] = fmaf(a3,b2,acc[3][2]); acc[3][3] = fmaf(a3,b3,acc[3][3]);
        }
    }

#pragma unroll
    for (int r = 0; r < 4; r++) {
        int rg = row0 + i0 + r;
        int b  = rg >> 11;           // rg / 2048
        int n  = rg & (NN - 1);
#pragma unroll
        for (int c = 0; c < 4; c++) {
            int cg = col0 + j0 + c;
            int h  = cg >> 5;
            int dk = cg & 31;
            Y[(((b * HH + h) * NN) + n) * DKK + dk] = acc[r][c];
        }
    }
}

// ---------------------------------------------------------------------------
// Kernel 2: fused attention (scores + edge + mask + online softmax + PV).
// One block per (b*H+h, q-tile of 64). 256 threads: 16x16 thread grid,
// each thread owns a 4x4 tile of S and 4 rows x 2 dk-cols of O.
// ---------------------------------------------------------------------------
__global__ __launch_bounds__(256) void attn_kernel(
    const float* __restrict__ edge,
    const int*   __restrict__ mask)
{
    __shared__ float Qs[64][DKK + 1];
    __shared__ float Ks[64][DKK + 1];
    __shared__ float Vs[64][DKK + 1];
    __shared__ float Ps[64][65];

    const int bh = blockIdx.y;          // 0..31
    const int b  = bh >> 3;
    const int h  = bh & 7;
    const int q0 = blockIdx.x * 64;

    const float* Qp = g_Q + (size_t)bh * NN * DKK;
    const float* Kp = g_K + (size_t)bh * NN * DKK;
    const float* Vp = g_V + (size_t)bh * NN * DKK;

    const int t  = threadIdx.x;
    const int ti = t >> 4, tj = t & 15;
    const int i0 = ti * 4, j0 = tj * 4;
    const int dk0 = tj * 2;

    for (int idx = t; idx < 64 * DKK; idx += 256) {
        int r = idx >> 5, k = idx & 31;
        Qs[r][k] = Qp[(q0 + r) * DKK + k];
    }

    float mrow[4], lrow[4], acc0[4], acc1[4];
#pragma unroll
    for (int r = 0; r < 4; r++) { mrow[r] = -1e30f; lrow[r] = 0.f; acc0[r] = 0.f; acc1[r] = 0.f; }

    for (int m0 = 0; m0 < NN; m0 += 64) {
        __syncthreads();   // previous iter's Ps/Vs reads done
        for (int idx = t; idx < 64 * DKK; idx += 256) {
            int r = idx >> 5, k = idx & 31;
            Ks[r][k] = Kp[(m0 + r) * DKK + k];
            Vs[r][k] = Vp[(m0 + r) * DKK + k];
        }
        __syncthreads();

        // S = Q K^T  (4x4 per thread)
        float s[4][4];
#pragma unroll
        for (int r = 0; r < 4; r++)
#pragma unroll
            for (int c = 0; c < 4; c++) s[r][c] = 0.f;

#pragma unroll
        for (int k = 0; k < DKK; k++) {
            float a0 = Qs[i0+0][k], a1 = Qs[i0+1][k], a2 = Qs[i0+2][k], a3 = Qs[i0+3][k];
            float b0 = Ks[j0+0][k], b1 = Ks[j0+1][k], b2 = Ks[j0+2][k], b3 = Ks[j0+3][k];
            s[0][0] = fmaf(a0,b0,s[0][0]); s[0][1] = fmaf(a0,b1,s[0][1]);
            s[0][2] = fmaf(a0,b2,s[0][2]); s[0][3] = fmaf(a0,b3,s[0][3]);
            s[1][0] = fmaf(a1,b0,s[1][0]); s[1][1] = fmaf(a1,b1,s[1][1]);
            s[1][2] = fmaf(a1,b2,s[1][2]); s[1][3] = fmaf(a1,b3,s[1][3]);
            s[2][0] = fmaf(a2,b0,s[2][0]); s[2][1] = fmaf(a2,b1,s[2][1]);
            s[2][2] = fmaf(a2,b2,s[2][2]); s[2][3] = fmaf(a2,b3,s[2][3]);
            s[3][0] = fmaf(a3,b0,s[3][0]); s[3][1] = fmaf(a3,b1,s[3][1]);
            s[3][2] = fmaf(a3,b2,s[3][2]); s[3][3] = fmaf(a3,b3,s[3][3]);
        }

        // scale + edge bias + mask  (vectorized 16B loads, coalesced)
#pragma unroll
        for (int r = 0; r < 4; r++) {
            int base = ((b * NN) + q0 + i0 + r) * NN + m0 + j0;
            float4 e = *reinterpret_cast<const float4*>(edge + base);
            int4  mk = *reinterpret_cast<const int4*>(mask + base);
            s[r][0] = mk.x ? fmaf(s[r][0], INV_SCALE, e.x) : -1e9f;
            s[r][1] = mk.y ? fmaf(s[r][1], INV_SCALE, e.y) : -1e9f;
            s[r][2] = mk.z ? fmaf(s[r][2], INV_SCALE, e.z) : -1e9f;
            s[r][3] = mk.w ? fmaf(s[r][3], INV_SCALE, e.w) : -1e9f;
        }

        // online softmax: row groups are 16 consecutive lanes (shfl-xor reduce)
#pragma unroll
        for (int r = 0; r < 4; r++) {
            float mx = fmaxf(fmaxf(s[r][0], s[r][1]), fmaxf(s[r][2], s[r][3]));
            mx = fmaxf(mx, __shfl_xor_sync(0xffffffffu, mx, 1));
            mx = fmaxf(mx, __shfl_xor_sync(0xffffffffu, mx, 2));
            mx = fmaxf(mx, __shfl_xor_sync(0xffffffffu, mx, 4));
            mx = fmaxf(mx, __shfl_xor_sync(0xffffffffu, mx, 8));
            float mn   = fmaxf(mrow[r], mx);
            float corr = __expf(mrow[r] - mn);
            mrow[r] = mn;
            float p0 = __expf(s[r][0] - mn);
            float p1 = __expf(s[r][1] - mn);
            float p2 = __expf(s[r][2] - mn);
            float p3 = __expf(s[r][3] - mn);
            float rs = (p0 + p1) + (p2 + p3);
            rs += __shfl_xor_sync(0xffffffffu, rs, 1);
            rs += __shfl_xor_sync(0xffffffffu, rs, 2);
            rs += __shfl_xor_sync(0xffffffffu, rs, 4);
            rs += __shfl_xor_sync(0xffffffffu, rs, 8);
            lrow[r] = lrow[r] * corr + rs;
            acc0[r] *= corr;
            acc1[r] *= corr;
            Ps[i0 + r][j0 + 0] = p0;
            Ps[i0 + r][j0 + 1] = p1;
            Ps[i0 + r][j0 + 2] = p2;
            Ps[i0 + r][j0 + 3] = p3;
        }
        __syncthreads();

        // O += P V   (each thread: 4 rows x 2 dk columns)
#pragma unroll 8
        for (int j = 0; j < 64; j++) {
            float v0 = Vs[j][dk0];
            float v1 = Vs[j][dk0 + 1];
#pragma unroll
            for (int r = 0; r < 4; r++) {
                float p = Ps[i0 + r][j];
                acc0[r] = fmaf(p, v0, acc0[r]);
                acc1[r] = fmaf(p, v1, acc1[r]);
            }
        }
    }

#pragma unroll
    for (int r = 0; r < 4; r++) {
        float invl = 1.0f / lrow[r];
        int n = q0 + i0 + r;
        int o = ((b * NN) + n) * DD + h * DKK + dk0;
        g_AO[o]     = acc0[r] * invl;
        g_AO[o + 1] = acc1[r] * invl;
    }
}

// ---------------------------------------------------------------------------
// Kernel 3: output projection.  out = AO @ Wo^T + bo
// ---------------------------------------------------------------------------
__global__ __launch_bounds__(256) void proj_kernel(
    const float* __restrict__ Wo,
    const float* __restrict__ bo,
    float* __restrict__ out)
{
    __shared__ float Xs[64][33];
    __shared__ float Ws[64][33];

    const int row0 = blockIdx.x * 64;
    const int col0 = blockIdx.y * 64;
    const int t  = threadIdx.x;
    const int ti = t >> 4, tj = t & 15;
    const int i0 = ti * 4, j0 = tj * 4;

    float acc[4][4];
#pragma unroll
    for (int r = 0; r < 4; r++)
#pragma unroll
        for (int c = 0; c < 4; c++) acc[r][c] = 0.f;

    for (int k0 = 0; k0 < DD; k0 += 32) {
        __syncthreads();
        for (int idx = t; idx < 64 * 32; idx += 256) {
            int r = idx >> 5, k = idx & 31;
            Xs[r][k] = g_AO[(row0 + r) * DD + k0 + k];
            Ws[r][k] = Wo[(col0 + r) * DD + k0 + k];
        }
        __syncthreads();
#pragma unroll
        for (int k = 0; k < 32; k++) {
            float a0 = Xs[i0+0][k], a1 = Xs[i0+1][k], a2 = Xs[i0+2][k], a3 = Xs[i0+3][k];
            float b0 = Ws[j0+0][k], b1 = Ws[j0+1][k], b2 = Ws[j0+2][k], b3 = Ws[j0+3][k];
            acc[0][0] = fmaf(a0,b0,acc[0][0]); acc[0][1] = fmaf(a0,b1,acc[0][1]);
            acc[0][2] = fmaf(a0,b2,acc[0][2]); acc[0][3] = fmaf(a0,b3,acc[0][3]);
            acc[1][0] = fmaf(a1,b0,acc[1][0]); acc[1][1] = fmaf(a1,b1,acc[1][1]);
            acc[1][2] = fmaf(a1,b2,acc[1][2]); acc[1][3] = fmaf(a1,b3,acc[1][3]);
            acc[2][0] = fmaf(a2,b0,acc[2][0]); acc[2][1] = fmaf(a2,b1,acc[2][1]);
            acc[2][2] = fmaf(a2,b2,acc[2][2]); acc[2][3] = fmaf(a2,b3,acc[2][3]);
            acc[3][0] = fmaf(a3,b0,acc[3][0]); acc[3][1] = fmaf(a3,b1,acc[3][1]);
            acc[3][2] = fmaf(a3,b2,acc[3][2]); acc[3][3] = fmaf(a3,b3,acc[3][3]);
        }
    }

#pragma unroll
    for (int r = 0; r < 4; r++) {
        int rg = row0 + i0 + r;
#pragma unroll
        for (int c = 0; c < 4; c++) {
            int cg = col0 + j0 + c;
            out[rg * DD + cg] = acc[r][c] + bo[cg];
        }
    }
}

// ---------------------------------------------------------------------------
extern "C" void kernel_launch(void* const* d_in, const int* in_sizes, int n_in,
                              void* d_out, int out_size)
{
    const float* x    = (const float*)d_in[0];
    const float* edge = (const float*)d_in[1];
    const int*   mask = (const int*)  d_in[2];
    const float* wq   = (const float*)d_in[3];
    const float* wk   = (const float*)d_in[4];
    const float* wv   = (const float*)d_in[5];
    const float* wo   = (const float*)d_in[6];
    const float* bo   = (const float*)d_in[7];
    float* out = (float*)d_out;

    dim3 g1((BB * NN) / 64, DD / 64, 3);
    qkv_kernel<<<g1, 256>>>(x, wq, wk, wv);

    dim3 g2(NN / 64, BB * HH);
    attn_kernel<<<g2, 256>>>(edge, mask);

    dim3 g3((BB * NN) / 64, DD / 64);
    proj_kernel<<<g3, 256>>>(wo, bo, out);
}

// round 3
// speedup vs baseline: 1.1256x; 1.1256x over previous
#include <cuda_runtime.h>
#include <cuda_fp16.h>
#include <mma.h>

using namespace nvcuda;

#define BB  4
#define NN  2048
#define DD  256
#define HH  8
#define DKK 32
#define INV_SCALE 0.17677669529663687f   // 1/sqrt(32)

// Scratch (device globals; allocation-free per harness rules)
__device__ float g_Q [BB*HH*NN*DKK];   // [bh][n][dk]
__device__ float g_K [BB*HH*NN*DKK];
__device__ float g_V [BB*HH*NN*DKK];
__device__ float g_AO[BB*NN*DD];

#define LDH 40   // half-tile pad (multiple of 8)
#define LDS 72   // fp32 S / half P pad (multiple of 8)
#define LDO 40   // fp32 PV-out pad (multiple of 4)

typedef wmma::fragment<wmma::matrix_a, 16,16,16, __half, wmma::row_major> FragA;
typedef wmma::fragment<wmma::matrix_b, 16,16,16, __half, wmma::col_major> FragBc;
typedef wmma::fragment<wmma::matrix_b, 16,16,16, __half, wmma::row_major> FragBr;
typedef wmma::fragment<wmma::accumulator, 16,16,16, float> FragC;

// Load a 64x32 fp32 tile (row stride `stride`) and split into hi/lo fp16 planes.
__device__ __forceinline__ void load_split(const float* __restrict__ g, int stride,
                                           __half (*H)[LDH], __half (*L)[LDH], int t)
{
    for (int i = t; i < 1024; i += 256) {
        int r = i >> 4, c = (i & 15) << 1;
        float2 v = *reinterpret_cast<const float2*>(g + (size_t)r * stride + c);
        __half h0 = __float2half_rn(v.x);
        __half h1 = __float2half_rn(v.y);
        H[r][c]     = h0;
        H[r][c + 1] = h1;
        L[r][c]     = __float2half_rn(v.x - __half2float(h0));
        L[r][c + 1] = __float2half_rn(v.y - __half2float(h1));
    }
}

// ---------------------------------------------------------------------------
// Linear kernel: Y = src @ W^T (+ bias).  64x64 tile, hi/lo split WMMA.
// mode 0: qkv (blockIdx.z selects W and Q/K/V dest, head-split scatter)
// mode 1: out-projection (reads g_AO, adds bias, writes out)
// ---------------------------------------------------------------------------
__global__ __launch_bounds__(256) void lin_kernel(
    const float* __restrict__ src,
    const float* __restrict__ W0,
    const float* __restrict__ W1,
    const float* __restrict__ W2,
    const float* __restrict__ bo,
    float* __restrict__ out,
    int mode)
{
    __shared__ __half Xh[64][LDH], Xl[64][LDH], Wh[64][LDH], Wl[64][LDH];
    __shared__ float  C[64][LDS];

    const int z = blockIdx.z;
    const float* A = (mode == 1) ? (const float*)g_AO : src;
    const float* W = (mode == 1) ? W0 : (z == 0 ? W0 : (z == 1 ? W1 : W2));

    const int row0 = blockIdx.x * 64;
    const int col0 = blockIdx.y * 64;
    const int t = threadIdx.x;
    const int w = t >> 5;
    const int rb = w >> 1;
    const int cb0 = (w & 1) * 2;

    FragC c[2];
    wmma::fill_fragment(c[0], 0.f);
    wmma::fill_fragment(c[1], 0.f);

    for (int k0 = 0; k0 < DD; k0 += 32) {
        __syncthreads();
        load_split(A + (size_t)row0 * DD + k0, DD, Xh, Xl, t);
        load_split(W + (size_t)col0 * DD + k0, DD, Wh, Wl, t);
        __syncthreads();
#pragma unroll
        for (int ks = 0; ks < 2; ks++) {
            FragA ah, al;
            wmma::load_matrix_sync(ah, &Xh[rb * 16][ks * 16], LDH);
            wmma::load_matrix_sync(al, &Xl[rb * 16][ks * 16], LDH);
#pragma unroll
            for (int q = 0; q < 2; q++) {
                int cb = cb0 + q;
                FragBc bh, bl;
                wmma::load_matrix_sync(bh, &Wh[cb * 16][ks * 16], LDH);
                wmma::load_matrix_sync(bl, &Wl[cb * 16][ks * 16], LDH);
                wmma::mma_sync(c[q], ah, bh, c[q]);
                wmma::mma_sync(c[q], ah, bl, c[q]);
                wmma::mma_sync(c[q], al, bh, c[q]);
            }
        }
    }

    wmma::store_matrix_sync(&C[rb * 16][cb0 * 16],       c[0], LDS, wmma::mem_row_major);
    wmma::store_matrix_sync(&C[rb * 16][(cb0 + 1) * 16], c[1], LDS, wmma::mem_row_major);
    __syncthreads();

    if (mode == 0) {
        float* Y = (z == 0) ? g_Q : (z == 1) ? g_K : g_V;
        for (int i = t; i < 4096; i += 256) {
            int r = i >> 6, cc = i & 63;
            int rg = row0 + r;
            int b  = rg >> 11;
            int n  = rg & (NN - 1);
            int cg = col0 + cc;
            int h  = cg >> 5;
            int dk = cg & 31;
            Y[(((size_t)(b * HH + h) * NN) + n) * DKK + dk] = C[r][cc];
        }
    } else {
        for (int i = t; i < 4096; i += 256) {
            int r = i >> 6, cc = i & 63;
            out[(size_t)(row0 + r) * DD + col0 + cc] = C[r][cc] + bo[col0 + cc];
        }
    }
}

// ---------------------------------------------------------------------------
// Attention kernel: per (h, b, q-tile of 64) CTA; flash loop over 64-col tiles.
// grid = (HH, BB * NN/64), block = 256 (8 warps).
// ---------------------------------------------------------------------------
#define SM_Q   0
#define SM_K   (SM_Q + 2 * 64 * LDH * 2)     // after Qh,Ql
#define SM_V   (SM_K + 2 * 64 * LDH * 2)
#define SM_S   (SM_V + 2 * 64 * LDH * 2)     // fp32 [64][LDS]; aliased by PV-out
#define SM_P   (SM_S + 64 * LDS * 4)         // Ph,Pl [64][LDS] halves
#define SM_TOT (SM_P + 2 * 64 * LDS * 2)

__global__ __launch_bounds__(256) void attn_kernel(
    const float* __restrict__ edge,
    const int*   __restrict__ mask)
{
    extern __shared__ char sm[];
    __half (*Qh)[LDH] = (__half(*)[LDH])(sm + SM_Q);
    __half (*Ql)[LDH] = (__half(*)[LDH])(sm + SM_Q + 64 * LDH * 2);
    __half (*Kh)[LDH] = (__half(*)[LDH])(sm + SM_K);
    __half (*Kl)[LDH] = (__half(*)[LDH])(sm + SM_K + 64 * LDH * 2);
    __half (*Vh)[LDH] = (__half(*)[LDH])(sm + SM_V);
    __half (*Vl)[LDH] = (__half(*)[LDH])(sm + SM_V + 64 * LDH * 2);
    float  (*S)[LDS]  = (float (*)[LDS])(sm + SM_S);
    float  (*PV)[LDO] = (float (*)[LDO])(sm + SM_S);          // alias
    __half (*Ph)[LDS] = (__half(*)[LDS])(sm + SM_P);
    __half (*Pl)[LDS] = (__half(*)[LDS])(sm + SM_P + 64 * LDS * 2);

    const int h  = blockIdx.x;
    const int b  = blockIdx.y >> 5;
    const int qt = blockIdx.y & 31;
    const int q0 = qt * 64;
    const int bh = b * HH + h;

    const float* Qg = g_Q + (size_t)bh * NN * DKK;
    const float* Kg = g_K + (size_t)bh * NN * DKK;
    const float* Vg = g_V + (size_t)bh * NN * DKK;

    const int t    = threadIdx.x;
    const int w    = t >> 5;
    const int rb   = w >> 1;
    const int cb0  = (w & 1) * 2;      // S col-block pair
    const int cbv  = w & 1;            // PV col-block

    // softmax / O ownership: 4 threads per row
    const int r  = t >> 2;             // row 0..63
    const int cg = t & 3;
    const int cc = cg * 16;            // softmax col window
    const int c0 = cg * 8;             // O col window (32 dk)

    load_split(Qg + (size_t)q0 * DKK, DKK, Qh, Ql, t);

    float O[8];
#pragma unroll
    for (int i = 0; i < 8; i++) O[i] = 0.f;
    float m_run = -1e30f, l_run = 0.f, corr_save = 1.f;

    for (int tile = 0; tile < 32; tile++) {
        const int m0 = tile * 64;

        // fold previous tile's PV output into O (PV aliases S; safe pre-sync)
        if (tile > 0) {
#pragma unroll
            for (int i = 0; i < 8; i++)
                O[i] = O[i] * corr_save + PV[r][c0 + i];
        }

        load_split(Kg + (size_t)m0 * DKK, DKK, Kh, Kl, t);
        load_split(Vg + (size_t)m0 * DKK, DKK, Vh, Vl, t);
        __syncthreads();

        // ---- S = Q K^T ----
        {
            FragC cS[2];
            wmma::fill_fragment(cS[0], 0.f);
            wmma::fill_fragment(cS[1], 0.f);
#pragma unroll
            for (int ks = 0; ks < 2; ks++) {
                FragA ah, al;
                wmma::load_matrix_sync(ah, &Qh[rb * 16][ks * 16], LDH);
                wmma::load_matrix_sync(al, &Ql[rb * 16][ks * 16], LDH);
#pragma unroll
                for (int q = 0; q < 2; q++) {
                    int cb = cb0 + q;
                    FragBc bhf, blf;
                    wmma::load_matrix_sync(bhf, &Kh[cb * 16][ks * 16], LDH);
                    wmma::load_matrix_sync(blf, &Kl[cb * 16][ks * 16], LDH);
                    wmma::mma_sync(cS[q], ah, bhf, cS[q]);
                    wmma::mma_sync(cS[q], ah, blf, cS[q]);
                    wmma::mma_sync(cS[q], al, bhf, cS[q]);
                }
            }
            wmma::store_matrix_sync(&S[rb * 16][cb0 * 16],       cS[0], LDS, wmma::mem_row_major);
            wmma::store_matrix_sync(&S[rb * 16][(cb0 + 1) * 16], cS[1], LDS, wmma::mem_row_major);
        }
        __syncthreads();

        // ---- softmax (scale + edge + mask, online max/sum) ----
        {
            float sv[16];
            float mloc = -1e30f;
            const size_t ebase = ((size_t)(b * NN) + q0 + r) * NN + m0 + cc;
#pragma unroll
            for (int i = 0; i < 4; i++) {
                float4 e4 = *reinterpret_cast<const float4*>(edge + ebase + 4 * i);
                int4   m4 = *reinterpret_cast<const int4*>  (mask + ebase + 4 * i);
                float s0 = S[r][cc + 4 * i + 0];
                float s1 = S[r][cc + 4 * i + 1];
                float s2 = S[r][cc + 4 * i + 2];
                float s3 = S[r][cc + 4 * i + 3];
                sv[4*i+0] = m4.x ? fmaf(s0, INV_SCALE, e4.x) : -1e9f;
                sv[4*i+1] = m4.y ? fmaf(s1, INV_SCALE, e4.y) : -1e9f;
                sv[4*i+2] = m4.z ? fmaf(s2, INV_SCALE, e4.z) : -1e9f;
                sv[4*i+3] = m4.w ? fmaf(s3, INV_SCALE, e4.w) : -1e9f;
                mloc = fmaxf(mloc, fmaxf(fmaxf(sv[4*i], sv[4*i+1]), fmaxf(sv[4*i+2], sv[4*i+3])));
            }
            mloc = fmaxf(mloc, __shfl_xor_sync(0xffffffffu, mloc, 1));
            mloc = fmaxf(mloc, __shfl_xor_sync(0xffffffffu, mloc, 2));
            float mnew = fmaxf(m_run, mloc);
            corr_save  = __expf(m_run - mnew);
            m_run = mnew;
            float lsum = 0.f;
#pragma unroll
            for (int i = 0; i < 16; i++) {
                float p = __expf(sv[i] - mnew);
                lsum += p;
                __half ph = __float2half_rn(p);
                Ph[r][cc + i] = ph;
                Pl[r][cc + i] = __float2half_rn(p - __half2float(ph));
            }
            lsum += __shfl_xor_sync(0xffffffffu, lsum, 1);
            lsum += __shfl_xor_sync(0xffffffffu, lsum, 2);
            l_run = l_run * corr_save + lsum;
        }
        __syncthreads();

        // ---- PVout = P V ----
        {
            FragC cO;
            wmma::fill_fragment(cO, 0.f);
#pragma unroll
            for (int ks = 0; ks < 4; ks++) {
                FragA ah, al;
                wmma::load_matrix_sync(ah, &Ph[rb * 16][ks * 16], LDS);
                wmma::load_matrix_sync(al, &Pl[rb * 16][ks * 16], LDS);
                FragBr bhf, blf;
                wmma::load_matrix_sync(bhf, &Vh[ks * 16][cbv * 16], LDH);
                wmma::load_matrix_sync(blf, &Vl[ks * 16][cbv * 16], LDH);
                wmma::mma_sync(cO, ah, bhf, cO);
                wmma::mma_sync(cO, ah, blf, cO);
                wmma::mma_sync(cO, al, bhf, cO);
            }
            wmma::store_matrix_sync(&PV[rb * 16][cbv * 16], cO, LDO, wmma::mem_row_major);
        }
        __syncthreads();
    }

    // final fold + normalize + store
#pragma unroll
    for (int i = 0; i < 8; i++)
        O[i] = O[i] * corr_save + PV[r][c0 + i];
    float invl = 1.0f / l_run;
    size_t ob = ((size_t)(b * NN) + q0 + r) * DD + h * DKK + c0;
#pragma unroll
    for (int i = 0; i < 8; i++)
        g_AO[ob + i] = O[i] * invl;
}

// ---------------------------------------------------------------------------
extern "C" void kernel_launch(void* const* d_in, const int* in_sizes, int n_in,
                              void* d_out, int out_size)
{
    const float* x    = (const float*)d_in[0];
    const float* edge = (const float*)d_in[1];
    const int*   mask = (const int*)  d_in[2];
    const float* wq   = (const float*)d_in[3];
    const float* wk   = (const float*)d_in[4];
    const float* wv   = (const float*)d_in[5];
    const float* wo   = (const float*)d_in[6];
    const float* bo   = (const float*)d_in[7];
    float* out = (float*)d_out;

    static bool attr_set = false;
    if (!attr_set) {
        cudaFuncSetAttribute(attn_kernel, cudaFuncAttributeMaxDynamicSharedMemorySize, SM_TOT);
        attr_set = true;
    }

    dim3 g1((BB * NN) / 64, DD / 64, 3);
    lin_kernel<<<g1, 256>>>(x, wq, wk, wv, nullptr, nullptr, 0);

    dim3 g2(HH, BB * (NN / 64));
    attn_kernel<<<g2, 256, SM_TOT>>>(edge, mask);

    dim3 g3((BB * NN) / 64, DD / 64, 1);
    lin_kernel<<<g3, 256>>>(x, wo, nullptr, nullptr, bo, out, 1);
}

// round 4
// speedup vs baseline: 1.1269x; 1.0012x over previous
#include <cuda_runtime.h>
#include <cuda_fp16.h>
#include <mma.h>

using namespace nvcuda;

#define BB  4
#define NN  2048
#define DD  256
#define HH  8
#define DKK 32
#define INV_SCALE 0.17677669529663687f   // 1/sqrt(32)

// Scratch (device globals; allocation-free per harness rules)
__device__ float g_Q [BB*HH*NN*DKK];   // [bh][n][dk]
__device__ float g_K [BB*HH*NN*DKK];
__device__ float g_V [BB*HH*NN*DKK];
__device__ float g_AO[BB*NN*DD];

#define LDH 40   // half-tile pad (multiple of 8)
#define LDS 72   // fp32 S / half P pad (multiple of 8)
#define LDO 40   // fp32 PV-out pad (multiple of 4)

typedef wmma::fragment<wmma::matrix_a, 16,16,16, __half, wmma::row_major> FragA;
typedef wmma::fragment<wmma::matrix_b, 16,16,16, __half, wmma::col_major> FragBc;
typedef wmma::fragment<wmma::matrix_b, 16,16,16, __half, wmma::row_major> FragBr;
typedef wmma::fragment<wmma::accumulator, 16,16,16, float> FragC;

// Load a 64x32 fp32 tile (row stride `stride`) and split into hi/lo fp16 planes.
__device__ __forceinline__ void load_split(const float* __restrict__ g, int stride,
                                           __half (*H)[LDH], __half (*L)[LDH], int t)
{
    for (int i = t; i < 1024; i += 256) {
        int r = i >> 4, c = (i & 15) << 1;
        float2 v = *reinterpret_cast<const float2*>(g + (size_t)r * stride + c);
        __half h0 = __float2half_rn(v.x);
        __half h1 = __float2half_rn(v.y);
        H[r][c]     = h0;
        H[r][c + 1] = h1;
        L[r][c]     = __float2half_rn(v.x - __half2float(h0));
        L[r][c + 1] = __float2half_rn(v.y - __half2float(h1));
    }
}

// ---------------------------------------------------------------------------
// Linear kernel: Y = src @ W^T (+ bias).  64x64 tile, hi/lo split WMMA.
// mode 0: qkv (blockIdx.z selects W and Q/K/V dest, head-split scatter)
// mode 1: out-projection (reads g_AO, adds bias, writes out)
// ---------------------------------------------------------------------------
__global__ __launch_bounds__(256) void lin_kernel(
    const float* __restrict__ src,
    const float* __restrict__ W0,
    const float* __restrict__ W1,
    const float* __restrict__ W2,
    const float* __restrict__ bo,
    float* __restrict__ out,
    int mode)
{
    __shared__ __half Xh[64][LDH], Xl[64][LDH], Wh[64][LDH], Wl[64][LDH];
    __shared__ float  C[64][LDS];

    const int z = blockIdx.z;
    const float* A = (mode == 1) ? (const float*)g_AO : src;
    const float* W = (mode == 1) ? W0 : (z == 0 ? W0 : (z == 1 ? W1 : W2));

    const int row0 = blockIdx.x * 64;
    const int col0 = blockIdx.y * 64;
    const int t = threadIdx.x;
    const int w = t >> 5;
    const int rb = w >> 1;
    const int cb0 = (w & 1) * 2;

    FragC c[2];
    wmma::fill_fragment(c[0], 0.f);
    wmma::fill_fragment(c[1], 0.f);

    for (int k0 = 0; k0 < DD; k0 += 32) {
        __syncthreads();
        load_split(A + (size_t)row0 * DD + k0, DD, Xh, Xl, t);
        load_split(W + (size_t)col0 * DD + k0, DD, Wh, Wl, t);
        __syncthreads();
#pragma unroll
        for (int ks = 0; ks < 2; ks++) {
            FragA ah, al;
            wmma::load_matrix_sync(ah, &Xh[rb * 16][ks * 16], LDH);
            wmma::load_matrix_sync(al, &Xl[rb * 16][ks * 16], LDH);
#pragma unroll
            for (int q = 0; q < 2; q++) {
                int cb = cb0 + q;
                FragBc bh, bl;
                wmma::load_matrix_sync(bh, &Wh[cb * 16][ks * 16], LDH);
                wmma::load_matrix_sync(bl, &Wl[cb * 16][ks * 16], LDH);
                wmma::mma_sync(c[q], ah, bh, c[q]);
                wmma::mma_sync(c[q], ah, bl, c[q]);
                wmma::mma_sync(c[q], al, bh, c[q]);
            }
        }
    }

    wmma::store_matrix_sync(&C[rb * 16][cb0 * 16],       c[0], LDS, wmma::mem_row_major);
    wmma::store_matrix_sync(&C[rb * 16][(cb0 + 1) * 16], c[1], LDS, wmma::mem_row_major);
    __syncthreads();

    if (mode == 0) {
        float* Y = (z == 0) ? g_Q : (z == 1) ? g_K : g_V;
        for (int i = t; i < 4096; i += 256) {
            int r = i >> 6, cc = i & 63;
            int rg = row0 + r;
            int b  = rg >> 11;
            int n  = rg & (NN - 1);
            int cg = col0 + cc;
            int h  = cg >> 5;
            int dk = cg & 31;
            Y[(((size_t)(b * HH + h) * NN) + n) * DKK + dk] = C[r][cc];
        }
    } else {
        for (int i = t; i < 4096; i += 256) {
            int r = i >> 6, cc = i & 63;
            out[(size_t)(row0 + r) * DD + col0 + cc] = C[r][cc] + bo[col0 + cc];
        }
    }
}

// ---------------------------------------------------------------------------
// Attention kernel: per (h, b, q-tile of 64) CTA; flash loop over 64-col tiles.
// grid = (HH, BB * NN/64), block = 256 (8 warps).
// ---------------------------------------------------------------------------
#define SM_Q   0
#define SM_K   (SM_Q + 2 * 64 * LDH * 2)     // after Qh,Ql
#define SM_V   (SM_K + 2 * 64 * LDH * 2)
#define SM_S   (SM_V + 2 * 64 * LDH * 2)     // fp32 [64][LDS]; aliased by PV-out
#define SM_P   (SM_S + 64 * LDS * 4)         // Ph,Pl [64][LDS] halves
#define SM_TOT (SM_P + 2 * 64 * LDS * 2)

__global__ __launch_bounds__(256) void attn_kernel(
    const float* __restrict__ edge,
    const int*   __restrict__ mask)
{
    extern __shared__ char sm[];
    __half (*Qh)[LDH] = (__half(*)[LDH])(sm + SM_Q);
    __half (*Ql)[LDH] = (__half(*)[LDH])(sm + SM_Q + 64 * LDH * 2);
    __half (*Kh)[LDH] = (__half(*)[LDH])(sm + SM_K);
    __half (*Kl)[LDH] = (__half(*)[LDH])(sm + SM_K + 64 * LDH * 2);
    __half (*Vh)[LDH] = (__half(*)[LDH])(sm + SM_V);
    __half (*Vl)[LDH] = (__half(*)[LDH])(sm + SM_V + 64 * LDH * 2);
    float  (*S)[LDS]  = (float (*)[LDS])(sm + SM_S);
    float  (*PV)[LDO] = (float (*)[LDO])(sm + SM_S);          // alias
    __half (*Ph)[LDS] = (__half(*)[LDS])(sm + SM_P);
    __half (*Pl)[LDS] = (__half(*)[LDS])(sm + SM_P + 64 * LDS * 2);

    const int h  = blockIdx.x;
    const int b  = blockIdx.y >> 5;
    const int qt = blockIdx.y & 31;
    const int q0 = qt * 64;
    const int bh = b * HH + h;

    const float* Qg = g_Q + (size_t)bh * NN * DKK;
    const float* Kg = g_K + (size_t)bh * NN * DKK;
    const float* Vg = g_V + (size_t)bh * NN * DKK;

    const int t    = threadIdx.x;
    const int w    = t >> 5;
    const int rb   = w >> 1;
    const int cb0  = (w & 1) * 2;      // S col-block pair
    const int cbv  = w & 1;            // PV col-block

    // softmax / O ownership: 4 threads per row
    const int r  = t >> 2;             // row 0..63
    const int cg = t & 3;
    const int cc = cg * 16;            // softmax col window
    const int c0 = cg * 8;             // O col window (32 dk)

    load_split(Qg + (size_t)q0 * DKK, DKK, Qh, Ql, t);

    float O[8];
#pragma unroll
    for (int i = 0; i < 8; i++) O[i] = 0.f;
    float m_run = -1e30f, l_run = 0.f, corr_save = 1.f;

    for (int tile = 0; tile < 32; tile++) {
        const int m0 = tile * 64;

        // fold previous tile's PV output into O (PV aliases S; safe pre-sync)
        if (tile > 0) {
#pragma unroll
            for (int i = 0; i < 8; i++)
                O[i] = O[i] * corr_save + PV[r][c0 + i];
        }

        load_split(Kg + (size_t)m0 * DKK, DKK, Kh, Kl, t);
        load_split(Vg + (size_t)m0 * DKK, DKK, Vh, Vl, t);
        __syncthreads();

        // ---- S = Q K^T ----
        {
            FragC cS[2];
            wmma::fill_fragment(cS[0], 0.f);
            wmma::fill_fragment(cS[1], 0.f);
#pragma unroll
            for (int ks = 0; ks < 2; ks++) {
                FragA ah, al;
                wmma::load_matrix_sync(ah, &Qh[rb * 16][ks * 16], LDH);
                wmma::load_matrix_sync(al, &Ql[rb * 16][ks * 16], LDH);
#pragma unroll
                for (int q = 0; q < 2; q++) {
                    int cb = cb0 + q;
                    FragBc bhf, blf;
                    wmma::load_matrix_sync(bhf, &Kh[cb * 16][ks * 16], LDH);
                    wmma::load_matrix_sync(blf, &Kl[cb * 16][ks * 16], LDH);
                    wmma::mma_sync(cS[q], ah, bhf, cS[q]);
                    wmma::mma_sync(cS[q], ah, blf, cS[q]);
                    wmma::mma_sync(cS[q], al, bhf, cS[q]);
                }
            }
            wmma::store_matrix_sync(&S[rb * 16][cb0 * 16],       cS[0], LDS, wmma::mem_row_major);
            wmma::store_matrix_sync(&S[rb * 16][(cb0 + 1) * 16], cS[1], LDS, wmma::mem_row_major);
        }
        __syncthreads();

        // ---- softmax (scale + edge + mask, online max/sum) ----
        {
            float sv[16];
            float mloc = -1e30f;
            const size_t ebase = ((size_t)(b * NN) + q0 + r) * NN + m0 + cc;
#pragma unroll
            for (int i = 0; i < 4; i++) {
                float4 e4 = *reinterpret_cast<const float4*>(edge + ebase + 4 * i);
                int4   m4 = *reinterpret_cast<const int4*>  (mask + ebase + 4 * i);
                float s0 = S[r][cc + 4 * i + 0];
                float s1 = S[r][cc + 4 * i + 1];
                float s2 = S[r][cc + 4 * i + 2];
                float s3 = S[r][cc + 4 * i + 3];
                sv[4*i+0] = m4.x ? fmaf(s0, INV_SCALE, e4.x) : -1e9f;
                sv[4*i+1] = m4.y ? fmaf(s1, INV_SCALE, e4.y) : -1e9f;
                sv[4*i+2] = m4.z ? fmaf(s2, INV_SCALE, e4.z) : -1e9f;
                sv[4*i+3] = m4.w ? fmaf(s3, INV_SCALE, e4.w) : -1e9f;
                mloc = fmaxf(mloc, fmaxf(fmaxf(sv[4*i], sv[4*i+1]), fmaxf(sv[4*i+2], sv[4*i+3])));
            }
            mloc = fmaxf(mloc, __shfl_xor_sync(0xffffffffu, mloc, 1));
            mloc = fmaxf(mloc, __shfl_xor_sync(0xffffffffu, mloc, 2));
            float mnew = fmaxf(m_run, mloc);
            corr_save  = __expf(m_run - mnew);
            m_run = mnew;
            float lsum = 0.f;
#pragma unroll
            for (int i = 0; i < 16; i++) {
                float p = __expf(sv[i] - mnew);
                lsum += p;
                __half ph = __float2half_rn(p);
                Ph[r][cc + i] = ph;
                Pl[r][cc + i] = __float2half_rn(p - __half2float(ph));
            }
            lsum += __shfl_xor_sync(0xffffffffu, lsum, 1);
            lsum += __shfl_xor_sync(0xffffffffu, lsum, 2);
            l_run = l_run * corr_save + lsum;
        }
        __syncthreads();

        // ---- PVout = P V ----
        {
            FragC cO;
            wmma::fill_fragment(cO, 0.f);
#pragma unroll
            for (int ks = 0; ks < 4; ks++) {
                FragA ah, al;
                wmma::load_matrix_sync(ah, &Ph[rb * 16][ks * 16], LDS);
                wmma::load_matrix_sync(al, &Pl[rb * 16][ks * 16], LDS);
                FragBr bhf, blf;
                wmma::load_matrix_sync(bhf, &Vh[ks * 16][cbv * 16], LDH);
                wmma::load_matrix_sync(blf, &Vl[ks * 16][cbv * 16], LDH);
                wmma::mma_sync(cO, ah, bhf, cO);
                wmma::mma_sync(cO, ah, blf, cO);
                wmma::mma_sync(cO, al, bhf, cO);
            }
            wmma::store_matrix_sync(&PV[rb * 16][cbv * 16], cO, LDO, wmma::mem_row_major);
        }
        __syncthreads();
    }

    // final fold + normalize + store
#pragma unroll
    for (int i = 0; i < 8; i++)
        O[i] = O[i] * corr_save + PV[r][c0 + i];
    float invl = 1.0f / l_run;
    size_t ob = ((size_t)(b * NN) + q0 + r) * DD + h * DKK + c0;
#pragma unroll
    for (int i = 0; i < 8; i++)
        g_AO[ob + i] = O[i] * invl;
}

// ---------------------------------------------------------------------------
extern "C" void kernel_launch(void* const* d_in, const int* in_sizes, int n_in,
                              void* d_out, int out_size)
{
    const float* x    = (const float*)d_in[0];
    const float* edge = (const float*)d_in[1];
    const int*   mask = (const int*)  d_in[2];
    const float* wq   = (const float*)d_in[3];
    const float* wk   = (const float*)d_in[4];
    const float* wv   = (const float*)d_in[5];
    const float* wo   = (const float*)d_in[6];
    const float* bo   = (const float*)d_in[7];
    float* out = (float*)d_out;

    static bool attr_set = false;
    if (!attr_set) {
        cudaFuncSetAttribute(attn_kernel, cudaFuncAttributeMaxDynamicSharedMemorySize, SM_TOT);
        attr_set = true;
    }

    dim3 g1((BB * NN) / 64, DD / 64, 3);
    lin_kernel<<<g1, 256>>>(x, wq, wk, wv, nullptr, nullptr, 0);

    dim3 g2(HH, BB * (NN / 64));
    attn_kernel<<<g2, 256, SM_TOT>>>(edge, mask);

    dim3 g3((BB * NN) / 64, DD / 64, 1);
    lin_kernel<<<g3, 256>>>(x, wo, nullptr, nullptr, bo, out, 1);
}

// round 6
// speedup vs baseline: 1.7138x; 1.5208x over previous
#include <cuda_runtime.h>
#include <cuda_fp16.h>
#include <mma.h>
#include <cstdint>
using namespace nvcuda;

#define BB  4
#define NN  2048
#define DD  256
#define HH  8
#define DKK 32
#define INV_SCALE 0.17677669529663687f

__device__ __half g_Qs [BB*HH*NN*64];   // [bh][n][hi32|lo32], Q pre-scaled
__device__ __half g_Ks [BB*HH*NN*64];   // [bh][n][hi32|lo32]
__device__ __half g_Vth[BB*HH*DKK*NN];  // [bh][dk][n]
__device__ __half g_Vtl[BB*HH*DKK*NN];
__device__ float  g_AO [BB*NN*DD];

// ---------------- fast exp on FMA pipe (no MUFU) ----------------
__device__ __forceinline__ float fexp(float x){
    x = fmaxf(x, -80.f);
    float t = x * 1.4426950408889634f;
    float y = t + 12582912.f;                       // round-to-nearest int trick
    int   n = __float_as_int(y) - 0x4B400000;
    float f = t - (y - 12582912.f);                 // f in [-0.5, 0.5]
    float r = f * 0.6931471805599453f;
    float p = fmaf(r, 8.3333333e-3f, 4.1666667e-2f);
    p = fmaf(p, r, 0.16666667f);
    p = fmaf(p, r, 0.5f);
    p = fmaf(p, r, 1.0f);
    p = fmaf(p, r, 1.0f);
    return __int_as_float(__float_as_int(p) + (n << 23));
}

__device__ __forceinline__ void mma16816(float* c, const uint32_t* a, const uint32_t* b){
    asm volatile("mma.sync.aligned.m16n8k16.row.col.f32.f16.f16.f32 "
        "{%0,%1,%2,%3}, {%4,%5,%6,%7}, {%8,%9}, {%0,%1,%2,%3};"
        : "+f"(c[0]), "+f"(c[1]), "+f"(c[2]), "+f"(c[3])
        : "r"(a[0]), "r"(a[1]), "r"(a[2]), "r"(a[3]), "r"(b[0]), "r"(b[1]));
}
__device__ __forceinline__ uint32_t h2u(__half2 v){ return *reinterpret_cast<uint32_t*>(&v); }

// ---------------- WMMA linear (qkv / out-proj) ----------------
#define LDHH 40
#define LDSS 72
typedef wmma::fragment<wmma::matrix_a,16,16,16,__half,wmma::row_major> FragA;
typedef wmma::fragment<wmma::matrix_b,16,16,16,__half,wmma::col_major> FragBc;
typedef wmma::fragment<wmma::accumulator,16,16,16,float> FragC;

__device__ __forceinline__ void load_split(const float* __restrict__ g, int stride,
                                           __half (*H)[LDHH], __half (*L)[LDHH], int t){
    for (int i=t;i<1024;i+=256){
        int r=i>>4, c=(i&15)<<1;
        float2 v=*reinterpret_cast<const float2*>(g+(size_t)r*stride+c);
        __half h0=__float2half_rn(v.x), h1=__float2half_rn(v.y);
        H[r][c]=h0; H[r][c+1]=h1;
        L[r][c]=__float2half_rn(v.x-__half2float(h0));
        L[r][c+1]=__float2half_rn(v.y-__half2float(h1));
    }
}

__global__ __launch_bounds__(256) void lin_kernel(
    const float* __restrict__ src, const float* __restrict__ W0,
    const float* __restrict__ W1,  const float* __restrict__ W2,
    const float* __restrict__ bo,  float* __restrict__ out, int mode)
{
    __shared__ __half Xh[64][LDHH], Xl[64][LDHH], Wh[64][LDHH], Wl[64][LDHH];
    __shared__ float  C[64][LDSS];
    const int z = blockIdx.z;
    const float* A = (mode==1) ? (const float*)g_AO : src;
    const float* W = (mode==1) ? W0 : (z==0?W0:(z==1?W1:W2));
    const int row0=blockIdx.x*64, col0=blockIdx.y*64;
    const int t=threadIdx.x, w=t>>5, rb=w>>1, cb0=(w&1)*2;

    FragC c[2]; wmma::fill_fragment(c[0],0.f); wmma::fill_fragment(c[1],0.f);
    for (int k0=0;k0<DD;k0+=32){
        __syncthreads();
        load_split(A+(size_t)row0*DD+k0, DD, Xh, Xl, t);
        load_split(W+(size_t)col0*DD+k0, DD, Wh, Wl, t);
        __syncthreads();
#pragma unroll
        for (int ks=0;ks<2;ks++){
            FragA ah,al;
            wmma::load_matrix_sync(ah,&Xh[rb*16][ks*16],LDHH);
            wmma::load_matrix_sync(al,&Xl[rb*16][ks*16],LDHH);
#pragma unroll
            for (int q=0;q<2;q++){
                FragBc bh,bl;
                wmma::load_matrix_sync(bh,&Wh[(cb0+q)*16][ks*16],LDHH);
                wmma::load_matrix_sync(bl,&Wl[(cb0+q)*16][ks*16],LDHH);
                wmma::mma_sync(c[q],ah,bh,c[q]);
                wmma::mma_sync(c[q],ah,bl,c[q]);
                wmma::mma_sync(c[q],al,bh,c[q]);
            }
        }
    }
    wmma::store_matrix_sync(&C[rb*16][cb0*16],    c[0],LDSS,wmma::mem_row_major);
    wmma::store_matrix_sync(&C[rb*16][(cb0+1)*16],c[1],LDSS,wmma::mem_row_major);
    __syncthreads();

    if (mode==0){
        for (int i=t;i<4096;i+=256){
            int r=i>>6, cc=i&63;
            int rg=row0+r, b=rg>>11, n=rg&(NN-1);
            int cg=col0+cc, h=cg>>5, dk=cg&31;
            size_t bh=(size_t)(b*HH+h);
            float v=C[r][cc]; if (z==0) v*=INV_SCALE;
            __half hi=__float2half_rn(v);
            __half lo=__float2half_rn(v-__half2float(hi));
            if (z==0){ g_Qs[(bh*NN+n)*64+dk]=hi; g_Qs[(bh*NN+n)*64+32+dk]=lo; }
            else if (z==1){ g_Ks[(bh*NN+n)*64+dk]=hi; g_Ks[(bh*NN+n)*64+32+dk]=lo; }
            else { g_Vth[(bh*DKK+dk)*NN+n]=hi; g_Vtl[(bh*DKK+dk)*NN+n]=lo; }
        }
    } else {
        for (int i=t;i<4096;i+=256){
            int r=i>>6, cc=i&63;
            out[(size_t)(row0+r)*DD+col0+cc] = C[r][cc] + bo[col0+cc];
        }
    }
}

// ---------------- FA2 attention on mma.sync ----------------
// grid (HH, BB*16); 256 threads = 8 warps x 16 q-rows. k-tiles of 64, dbl-buffered.
#define KP 72   // smem pitch (halves)

__global__ __launch_bounds__(256,2) void attn_kernel(
    const float* __restrict__ edge, const int* __restrict__ mask)
{
    __shared__ __half Ks[2][64][KP];
    __shared__ __half Vs[2][64][KP];   // rows 0-31: V^T hi, 32-63: V^T lo

    const int tid=threadIdx.x, w=tid>>5, lane=tid&31;
    const int h=blockIdx.x, b=blockIdx.y>>4, qt=blockIdx.y&15;
    const int q0=qt*128, bh=b*HH+h;
    const int r0=lane>>2, cq=lane&3;

    const __half* Qg = g_Qs + ((size_t)bh*NN + q0 + 16*w)*64;
    const __half* Kg = g_Ks + (size_t)bh*NN*64;
    const __half* VgH= g_Vth + (size_t)bh*DKK*NN;
    const __half* VgL= g_Vtl + (size_t)bh*DKK*NN;

    // Q fragments (persistent): [kstep][a0..a3], hi & lo
    uint32_t qh[2][4], ql[2][4];
#pragma unroll
    for (int ks=0;ks<2;ks++){
        int col=16*ks+2*cq;
        qh[ks][0]=*(const uint32_t*)(Qg+(size_t) r0   *64+col);
        qh[ks][1]=*(const uint32_t*)(Qg+(size_t)(r0+8)*64+col);
        qh[ks][2]=*(const uint32_t*)(Qg+(size_t) r0   *64+col+8);
        qh[ks][3]=*(const uint32_t*)(Qg+(size_t)(r0+8)*64+col+8);
        ql[ks][0]=*(const uint32_t*)(Qg+(size_t) r0   *64+32+col);
        ql[ks][1]=*(const uint32_t*)(Qg+(size_t)(r0+8)*64+32+col);
        ql[ks][2]=*(const uint32_t*)(Qg+(size_t) r0   *64+32+col+8);
        ql[ks][3]=*(const uint32_t*)(Qg+(size_t)(r0+8)*64+32+col+8);
    }

    float Oc[4][4];
#pragma unroll
    for (int i=0;i<4;i++){ Oc[i][0]=0.f; Oc[i][1]=0.f; Oc[i][2]=0.f; Oc[i][3]=0.f; }
    float mr0=-1e30f, mr1=-1e30f, l0=0.f, l1=0.f;

    const size_t erow = ((size_t)(b*NN)+q0+16*w+r0)*NN + 2*cq;

    // stage tile 0
#pragma unroll
    for (int q=0;q<2;q++){
        int g=tid+256*q; int row=g>>3, c8=(g&7)*8;
        *(uint4*)&Ks[0][row][c8] = *(const uint4*)(Kg+(size_t)row*64+c8);
    }
#pragma unroll
    for (int q=0;q<2;q++){
        int g=tid+256*q; int pl=g>>8, rr=(g>>3)&31, c8=(g&7)*8;
        const __half* src=(pl?VgL:VgH)+(size_t)rr*NN+c8;
        *(uint4*)&Vs[0][pl*32+rr][c8] = *(const uint4*)src;
    }
    __syncthreads();

#pragma unroll 1
    for (int t=0;t<32;t++){
        const int cur=t&1, m0=t*64;
        if (t<31){
            const int nxt=cur^1, m1=m0+64;
#pragma unroll
            for (int q=0;q<2;q++){
                int g=tid+256*q; int row=g>>3, c8=(g&7)*8;
                *(uint4*)&Ks[nxt][row][c8] = *(const uint4*)(Kg+(size_t)(m1+row)*64+c8);
            }
#pragma unroll
            for (int q=0;q<2;q++){
                int g=tid+256*q; int pl=g>>8, rr=(g>>3)&31, c8=(g&7)*8;
                const __half* src=(pl?VgL:VgH)+(size_t)rr*NN+m1+c8;
                *(uint4*)&Vs[nxt][pl*32+rr][c8] = *(const uint4*)src;
            }
        }

        // ---- S = Q K^T (8 n-tiles x 2 ksteps x 3 passes) ----
        float s[8][4];
#pragma unroll
        for (int j=0;j<8;j++){ s[j][0]=0.f; s[j][1]=0.f; s[j][2]=0.f; s[j][3]=0.f; }
#pragma unroll
        for (int j=0;j<8;j++){
            const __half* kr = &Ks[cur][8*j+r0][0];
#pragma unroll
            for (int ks=0;ks<2;ks++){
                int kc=16*ks+2*cq;
                uint32_t bhv[2]={*(const uint32_t*)(kr+kc),    *(const uint32_t*)(kr+kc+8)};
                uint32_t blv[2]={*(const uint32_t*)(kr+32+kc), *(const uint32_t*)(kr+32+kc+8)};
                mma16816(s[j], qh[ks], bhv);
                mma16816(s[j], qh[ks], blv);
                mma16816(s[j], ql[ks], bhv);
            }
        }

        // ---- edge + mask + online softmax (registers) ----
        const float* ep = edge + erow + m0;
        const int*   mp = mask + erow + m0;
        float mt0=-1e30f, mt1=-1e30f;
#pragma unroll
        for (int j=0;j<8;j++){
            float2 e0=*(const float2*)(ep+8*j);
            int2   k0=*(const int2*)  (mp+8*j);
            float2 e1=*(const float2*)(ep+8*j+(size_t)8*NN);
            int2   k1=*(const int2*)  (mp+8*j+(size_t)8*NN);
            s[j][0]=k0.x? s[j][0]+e0.x : -1e9f;
            s[j][1]=k0.y? s[j][1]+e0.y : -1e9f;
            s[j][2]=k1.x? s[j][2]+e1.x : -1e9f;
            s[j][3]=k1.y? s[j][3]+e1.y : -1e9f;
            mt0=fmaxf(mt0,fmaxf(s[j][0],s[j][1]));
            mt1=fmaxf(mt1,fmaxf(s[j][2],s[j][3]));
        }
        mt0=fmaxf(mt0,__shfl_xor_sync(0xffffffffu,mt0,1));
        mt0=fmaxf(mt0,__shfl_xor_sync(0xffffffffu,mt0,2));
        mt1=fmaxf(mt1,__shfl_xor_sync(0xffffffffu,mt1,1));
        mt1=fmaxf(mt1,__shfl_xor_sync(0xffffffffu,mt1,2));
        float mn0=fmaxf(mr0,mt0), mn1=fmaxf(mr1,mt1);
        float c0=fexp(mr0-mn0), c1=fexp(mr1-mn1);
        mr0=mn0; mr1=mn1;
        float ls0=0.f, ls1=0.f;
#pragma unroll
        for (int j=0;j<8;j++){
            s[j][0]=fexp(s[j][0]-mn0); s[j][1]=fexp(s[j][1]-mn0); ls0+=s[j][0]+s[j][1];
            s[j][2]=fexp(s[j][2]-mn1); s[j][3]=fexp(s[j][3]-mn1); ls1+=s[j][2]+s[j][3];
        }
        l0=l0*c0+ls0; l1=l1*c1+ls1;
#pragma unroll
        for (int nt=0;nt<4;nt++){ Oc[nt][0]*=c0; Oc[nt][1]*=c0; Oc[nt][2]*=c1; Oc[nt][3]*=c1; }

        // ---- O += P V (P from registers: hi/lo 3 passes) ----
#pragma unroll
        for (int i=0;i<4;i++){
            __half2 H0=__floats2half2_rn(s[2*i][0],  s[2*i][1]);
            __half2 H1=__floats2half2_rn(s[2*i][2],  s[2*i][3]);
            __half2 H2=__floats2half2_rn(s[2*i+1][0],s[2*i+1][1]);
            __half2 H3=__floats2half2_rn(s[2*i+1][2],s[2*i+1][3]);
            uint32_t ah[4]={h2u(H0),h2u(H1),h2u(H2),h2u(H3)};
            __half2 L0=__floats2half2_rn(s[2*i][0]-__low2float(H0),   s[2*i][1]-__high2float(H0));
            __half2 L1=__floats2half2_rn(s[2*i][2]-__low2float(H1),   s[2*i][3]-__high2float(H1));
            __half2 L2=__floats2half2_rn(s[2*i+1][0]-__low2float(H2), s[2*i+1][1]-__high2float(H2));
            __half2 L3=__floats2half2_rn(s[2*i+1][2]-__low2float(H3), s[2*i+1][3]-__high2float(H3));
            uint32_t al[4]={h2u(L0),h2u(L1),h2u(L2),h2u(L3)};
#pragma unroll
            for (int nt=0;nt<4;nt++){
                const __half* vr=&Vs[cur][8*nt+r0][16*i+2*cq];
                uint32_t bhv[2]={*(const uint32_t*)vr,           *(const uint32_t*)(vr+8)};
                const __half* vl=vr+32*KP;
                uint32_t blv[2]={*(const uint32_t*)vl,           *(const uint32_t*)(vl+8)};
                mma16816(Oc[nt], ah, bhv);
                mma16816(Oc[nt], ah, blv);
                mma16816(Oc[nt], al, bhv);
            }
        }
        __syncthreads();
    }

    // epilogue: reduce l across quad, normalize, store
    l0 += __shfl_xor_sync(0xffffffffu,l0,1);
    l0 += __shfl_xor_sync(0xffffffffu,l0,2);
    l1 += __shfl_xor_sync(0xffffffffu,l1,1);
    l1 += __shfl_xor_sync(0xffffffffu,l1,2);
    float inv0=1.0f/l0, inv1=1.0f/l1;
    float* op = g_AO + ((size_t)(b*NN)+q0+16*w+r0)*DD + h*DKK + 2*cq;
#pragma unroll
    for (int nt=0;nt<4;nt++){
        float2 v0={Oc[nt][0]*inv0, Oc[nt][1]*inv0};
        float2 v1={Oc[nt][2]*inv1, Oc[nt][3]*inv1};
        *(float2*)(op + 8*nt)          = v0;
        *(float2*)(op + 8*nt + 8*DD)   = v1;
    }
}

// ---------------------------------------------------------------------------
extern "C" void kernel_launch(void* const* d_in, const int* in_sizes, int n_in,
                              void* d_out, int out_size)
{
    const float* x    = (const float*)d_in[0];
    const float* edge = (const float*)d_in[1];
    const int*   mask = (const int*)  d_in[2];
    const float* wq   = (const float*)d_in[3];
    const float* wk   = (const float*)d_in[4];
    const float* wv   = (const float*)d_in[5];
    const float* wo   = (const float*)d_in[6];
    const float* bo   = (const float*)d_in[7];
    float* out = (float*)d_out;

    dim3 g1((BB*NN)/64, DD/64, 3);
    lin_kernel<<<g1,256>>>(x, wq, wk, wv, nullptr, nullptr, 0);

    dim3 g2(HH, BB*16);
    attn_kernel<<<g2,256>>>(edge, mask);

    dim3 g3((BB*NN)/64, DD/64, 1);
    lin_kernel<<<g3,256>>>(x, wo, nullptr, nullptr, bo, out, 1);
}

// round 7
// speedup vs baseline: 1.9956x; 1.1644x over previous
#include <cuda_runtime.h>
#include <cuda_fp16.h>
#include <mma.h>
#include <cstdint>
using namespace nvcuda;

#define BB  4
#define NN  2048
#define DD  256
#define HH  8
#define DKK 32
#define INV_SCALE 0.17677669529663687f

__device__ __half g_Qs [BB*HH*NN*64];   // [bh][n][hi32|lo32], Q pre-scaled
__device__ __half g_Ks [BB*HH*NN*64];
__device__ __half g_Vth[BB*HH*DKK*NN];  // [bh][dk][n]
__device__ __half g_Vtl[BB*HH*DKK*NN];
__device__ float  g_AO [BB*NN*DD];

__device__ __forceinline__ float fexp(float x){
    x = fmaxf(x, -80.f);
    float t = x * 1.4426950408889634f;
    float y = t + 12582912.f;
    int   n = __float_as_int(y) - 0x4B400000;
    float f = t - (y - 12582912.f);
    float r = f * 0.6931471805599453f;
    float p = fmaf(r, 8.3333333e-3f, 4.1666667e-2f);
    p = fmaf(p, r, 0.16666667f);
    p = fmaf(p, r, 0.5f);
    p = fmaf(p, r, 1.0f);
    p = fmaf(p, r, 1.0f);
    return __int_as_float(__float_as_int(p) + (n << 23));
}

__device__ __forceinline__ void mma16816(float* c, const uint32_t* a, const uint32_t* b){
    asm volatile("mma.sync.aligned.m16n8k16.row.col.f32.f16.f16.f32 "
        "{%0,%1,%2,%3}, {%4,%5,%6,%7}, {%8,%9}, {%0,%1,%2,%3};"
        : "+f"(c[0]), "+f"(c[1]), "+f"(c[2]), "+f"(c[3])
        : "r"(a[0]), "r"(a[1]), "r"(a[2]), "r"(a[3]), "r"(b[0]), "r"(b[1]));
}
__device__ __forceinline__ uint32_t h2u(__half2 v){ return *reinterpret_cast<uint32_t*>(&v); }
__device__ __forceinline__ uint32_t smem_u32(const void* p){
    uint32_t a;
    asm("{ .reg .u64 t; cvta.to.shared.u64 t, %1; cvt.u32.u64 %0, t; }" : "=r"(a) : "l"(p));
    return a;
}
__device__ __forceinline__ void ldsm4(uint32_t* r, uint32_t a){
    asm volatile("ldmatrix.sync.aligned.m8n8.x4.shared.b16 {%0,%1,%2,%3}, [%4];"
        : "=r"(r[0]),"=r"(r[1]),"=r"(r[2]),"=r"(r[3]) : "r"(a));
}
#define CP16(d,s) asm volatile("cp.async.cg.shared.global [%0], [%1], 16;\n"::"r"(d),"l"(s))
#define CPC()     asm volatile("cp.async.commit_group;\n":::"memory")
#define CPW0()    asm volatile("cp.async.wait_group 0;\n":::"memory")

// ---------------- WMMA linear ----------------
#define LDHH 40
#define LDSS 72
typedef wmma::fragment<wmma::matrix_a,16,16,16,__half,wmma::row_major> FragA;
typedef wmma::fragment<wmma::matrix_b,16,16,16,__half,wmma::col_major> FragBc;
typedef wmma::fragment<wmma::accumulator,16,16,16,float> FragC;

__device__ __forceinline__ void load_split(const float* __restrict__ g, int stride,
                                           __half (*H)[LDHH], __half (*L)[LDHH], int t){
    for (int i=t;i<1024;i+=256){
        int r=i>>4, c=(i&15)<<1;
        float2 v=*reinterpret_cast<const float2*>(g+(size_t)r*stride+c);
        __half h0=__float2half_rn(v.x), h1=__float2half_rn(v.y);
        H[r][c]=h0; H[r][c+1]=h1;
        L[r][c]=__float2half_rn(v.x-__half2float(h0));
        L[r][c+1]=__float2half_rn(v.y-__half2float(h1));
    }
}

__global__ __launch_bounds__(256) void lin_kernel(
    const float* __restrict__ src, const float* __restrict__ W0,
    const float* __restrict__ W1,  const float* __restrict__ W2,
    const float* __restrict__ bo,  float* __restrict__ out, int mode)
{
    __shared__ __half Xh[64][LDHH], Xl[64][LDHH], Wh[64][LDHH], Wl[64][LDHH];
    __shared__ float  C[64][LDSS];
    const int z = blockIdx.z;
    const float* A = (mode==1) ? (const float*)g_AO : src;
    const float* W = (mode==1) ? W0 : (z==0?W0:(z==1?W1:W2));
    const int row0=blockIdx.x*64, col0=blockIdx.y*64;
    const int t=threadIdx.x, w=t>>5, rb=w>>1, cb0=(w&1)*2;

    FragC c[2]; wmma::fill_fragment(c[0],0.f); wmma::fill_fragment(c[1],0.f);
    for (int k0=0;k0<DD;k0+=32){
        __syncthreads();
        load_split(A+(size_t)row0*DD+k0, DD, Xh, Xl, t);
        load_split(W+(size_t)col0*DD+k0, DD, Wh, Wl, t);
        __syncthreads();
#pragma unroll
        for (int ks=0;ks<2;ks++){
            FragA ah,al;
            wmma::load_matrix_sync(ah,&Xh[rb*16][ks*16],LDHH);
            wmma::load_matrix_sync(al,&Xl[rb*16][ks*16],LDHH);
#pragma unroll
            for (int q=0;q<2;q++){
                FragBc bh,bl;
                wmma::load_matrix_sync(bh,&Wh[(cb0+q)*16][ks*16],LDHH);
                wmma::load_matrix_sync(bl,&Wl[(cb0+q)*16][ks*16],LDHH);
                wmma::mma_sync(c[q],ah,bh,c[q]);
                wmma::mma_sync(c[q],ah,bl,c[q]);
                wmma::mma_sync(c[q],al,bh,c[q]);
            }
        }
    }
    wmma::store_matrix_sync(&C[rb*16][cb0*16],    c[0],LDSS,wmma::mem_row_major);
    wmma::store_matrix_sync(&C[rb*16][(cb0+1)*16],c[1],LDSS,wmma::mem_row_major);
    __syncthreads();

    if (mode==0){
        if (z<2){
            __half* dst = (z==0) ? g_Qs : g_Ks;
            for (int i=t;i<2048;i+=256){
                int r=i>>5, cp=(i&31)*2;
                int rg=row0+r, b=rg>>11, n=rg&(NN-1);
                int cg=col0+cp, h=cg>>5, dk=cg&31;
                float v0=C[r][cp], v1=C[r][cp+1];
                if (z==0){ v0*=INV_SCALE; v1*=INV_SCALE; }
                __half h0=__float2half_rn(v0), h1=__float2half_rn(v1);
                __half l0=__float2half_rn(v0-__half2float(h0));
                __half l1=__float2half_rn(v1-__half2float(h1));
                size_t base=((size_t)(b*HH+h)*NN+n)*64;
                *reinterpret_cast<__half2*>(dst+base+dk)    = __halves2half2(h0,h1);
                *reinterpret_cast<__half2*>(dst+base+32+dk) = __halves2half2(l0,l1);
            }
        } else {
            for (int i=t;i<2048;i+=256){
                int np=i&31, cc=i>>5;
                int rg=row0+np*2, b=rg>>11, n=rg&(NN-1);
                int cg=col0+cc, h=cg>>5, dk=cg&31;
                float v0=C[np*2][cc], v1=C[np*2+1][cc];
                __half h0=__float2half_rn(v0), h1=__float2half_rn(v1);
                __half l0=__float2half_rn(v0-__half2float(h0));
                __half l1=__float2half_rn(v1-__half2float(h1));
                size_t base=((size_t)(b*HH+h)*DKK+dk)*NN+n;
                *reinterpret_cast<__half2*>(g_Vth+base) = __halves2half2(h0,h1);
                *reinterpret_cast<__half2*>(g_Vtl+base) = __halves2half2(l0,l1);
            }
        }
    } else {
        for (int i=t;i<4096;i+=256){
            int r=i>>6, cc=i&63;
            out[(size_t)(row0+r)*DD+col0+cc] = C[r][cc] + bo[col0+cc];
        }
    }
}

// ---------------- FA2 attention: ldmatrix + cp.async ----------------
#define KP  72
#define KSZ (64*KP*2)

__global__ __launch_bounds__(256,2) void attn_kernel(
    const float* __restrict__ edge, const int* __restrict__ mask)
{
    __shared__ __half Ks[2][64][KP];
    __shared__ __half Vs[2][64][KP];   // rows 0-31 V^T hi, 32-63 V^T lo

    const int tid=threadIdx.x, w=tid>>5, lane=tid&31;
    const int h=blockIdx.x, b=blockIdx.y>>4, qt=blockIdx.y&15;
    const int q0=qt*128, bh=b*HH+h;
    const int r0=lane>>2, cq=lane&3;

    const __half* Qg = g_Qs + ((size_t)bh*NN + q0 + 16*w)*64;
    const __half* Kg = g_Ks + (size_t)bh*NN*64;
    const __half* VgH= g_Vth + (size_t)bh*DKK*NN;
    const __half* VgL= g_Vtl + (size_t)bh*DKK*NN;

    const uint32_t smbK = smem_u32(&Ks[0][0][0]);
    const uint32_t smbV = smem_u32(&Vs[0][0][0]);

    uint32_t qh[2][4], ql[2][4];
#pragma unroll
    for (int ks=0;ks<2;ks++){
        int col=16*ks+2*cq;
        qh[ks][0]=*(const uint32_t*)(Qg+(size_t) r0   *64+col);
        qh[ks][1]=*(const uint32_t*)(Qg+(size_t)(r0+8)*64+col);
        qh[ks][2]=*(const uint32_t*)(Qg+(size_t) r0   *64+col+8);
        qh[ks][3]=*(const uint32_t*)(Qg+(size_t)(r0+8)*64+col+8);
        ql[ks][0]=*(const uint32_t*)(Qg+(size_t) r0   *64+32+col);
        ql[ks][1]=*(const uint32_t*)(Qg+(size_t)(r0+8)*64+32+col);
        ql[ks][2]=*(const uint32_t*)(Qg+(size_t) r0   *64+32+col+8);
        ql[ks][3]=*(const uint32_t*)(Qg+(size_t)(r0+8)*64+32+col+8);
    }

    float Oc[4][4];
#pragma unroll
    for (int i=0;i<4;i++){ Oc[i][0]=0.f; Oc[i][1]=0.f; Oc[i][2]=0.f; Oc[i][3]=0.f; }
    float mr0=-1e30f, mr1=-1e30f, l0=0.f, l1=0.f;
    const size_t erow = ((size_t)(b*NN)+q0+16*w+r0)*NN + 2*cq;

    // stage tile 0 via cp.async
    {
        int g0=tid, g1=tid+256;
        int ra=g0>>3, ca=(g0&7)*8, rb_=g1>>3, cb=(g1&7)*8;
        CP16(smbK+(uint32_t)(ra*KP+ca)*2,  Kg+(size_t)ra*64+ca);
        CP16(smbK+(uint32_t)(rb_*KP+cb)*2, Kg+(size_t)rb_*64+cb);
        int p0=g0>>8, v0r=(g0>>3)&31, p1=g1>>8, v1r=(g1>>3)&31;
        CP16(smbV+(uint32_t)((p0*32+v0r)*KP+ca)*2, (p0?VgL:VgH)+(size_t)v0r*NN+ca);
        CP16(smbV+(uint32_t)((p1*32+v1r)*KP+cb)*2, (p1?VgL:VgH)+(size_t)v1r*NN+cb);
        CPC();
    }

#pragma unroll 1
    for (int tt=0;tt<32;tt++){
        const int cur=tt&1, m0=tt*64;
        CPW0();
        __syncthreads();
        if (tt<31){
            const uint32_t kb=smbK+(cur^1)*KSZ, vb=smbV+(cur^1)*KSZ;
            const int m1=m0+64;
            int g0=tid, g1=tid+256;
            int ra=g0>>3, ca=(g0&7)*8, rb_=g1>>3, cb=(g1&7)*8;
            CP16(kb+(uint32_t)(ra*KP+ca)*2,  Kg+(size_t)(m1+ra)*64+ca);
            CP16(kb+(uint32_t)(rb_*KP+cb)*2, Kg+(size_t)(m1+rb_)*64+cb);
            int p0=g0>>8, v0r=(g0>>3)&31, p1=g1>>8, v1r=(g1>>3)&31;
            CP16(vb+(uint32_t)((p0*32+v0r)*KP+ca)*2, (p0?VgL:VgH)+(size_t)v0r*NN+m1+ca);
            CP16(vb+(uint32_t)((p1*32+v1r)*KP+cb)*2, (p1?VgL:VgH)+(size_t)v1r*NN+m1+cb);
            CPC();
        }

        // ---- S = Q K^T ----
        float s[8][4];
#pragma unroll
        for (int j=0;j<8;j++){ s[j][0]=0.f; s[j][1]=0.f; s[j][2]=0.f; s[j][3]=0.f; }
        const uint32_t kbase = smbK + cur*KSZ + (uint32_t)((lane&7)*KP + (lane>>3)*8)*2;
#pragma unroll
        for (int j=0;j<8;j++){
            uint32_t bh4[4], bl4[4];
            uint32_t a = kbase + (uint32_t)(8*j*KP)*2;
            ldsm4(bh4, a);
            ldsm4(bl4, a + 64);
            mma16816(s[j], qh[0], &bh4[0]); mma16816(s[j], qh[1], &bh4[2]);
            mma16816(s[j], qh[0], &bl4[0]); mma16816(s[j], qh[1], &bl4[2]);
            mma16816(s[j], ql[0], &bh4[0]); mma16816(s[j], ql[1], &bh4[2]);
        }

        // ---- edge + mask + online softmax ----
        const float* ep = edge + erow + m0;
        const int*   mp = mask + erow + m0;
        float mt0=-1e30f, mt1=-1e30f;
#pragma unroll
        for (int j=0;j<8;j++){
            float2 e0=*(const float2*)(ep+8*j);
            int2   k0=*(const int2*)  (mp+8*j);
            float2 e1=*(const float2*)(ep+8*j+(size_t)8*NN);
            int2   k1=*(const int2*)  (mp+8*j+(size_t)8*NN);
            s[j][0]=k0.x? s[j][0]+e0.x : -1e9f;
            s[j][1]=k0.y? s[j][1]+e0.y : -1e9f;
            s[j][2]=k1.x? s[j][2]+e1.x : -1e9f;
            s[j][3]=k1.y? s[j][3]+e1.y : -1e9f;
            mt0=fmaxf(mt0,fmaxf(s[j][0],s[j][1]));
            mt1=fmaxf(mt1,fmaxf(s[j][2],s[j][3]));
        }
        mt0=fmaxf(mt0,__shfl_xor_sync(0xffffffffu,mt0,1));
        mt0=fmaxf(mt0,__shfl_xor_sync(0xffffffffu,mt0,2));
        mt1=fmaxf(mt1,__shfl_xor_sync(0xffffffffu,mt1,1));
        mt1=fmaxf(mt1,__shfl_xor_sync(0xffffffffu,mt1,2));
        float mn0=fmaxf(mr0,mt0), mn1=fmaxf(mr1,mt1);
        float c0=fexp(mr0-mn0), c1=fexp(mr1-mn1);
        mr0=mn0; mr1=mn1;
        float ls0=0.f, ls1=0.f;
#pragma unroll
        for (int j=0;j<8;j++){
            s[j][0]=fexp(s[j][0]-mn0); s[j][1]=fexp(s[j][1]-mn0); ls0+=s[j][0]+s[j][1];
            s[j][2]=fexp(s[j][2]-mn1); s[j][3]=fexp(s[j][3]-mn1); ls1+=s[j][2]+s[j][3];
        }
        l0=l0*c0+ls0; l1=l1*c1+ls1;
#pragma unroll
        for (int nt=0;nt<4;nt++){ Oc[nt][0]*=c0; Oc[nt][1]*=c0; Oc[nt][2]*=c1; Oc[nt][3]*=c1; }

        // ---- build P fragments ----
        uint32_t aH[4][4], aL[4][4];
#pragma unroll
        for (int i=0;i<4;i++){
            __half2 H0=__floats2half2_rn(s[2*i][0],  s[2*i][1]);
            __half2 H1=__floats2half2_rn(s[2*i][2],  s[2*i][3]);
            __half2 H2=__floats2half2_rn(s[2*i+1][0],s[2*i+1][1]);
            __half2 H3=__floats2half2_rn(s[2*i+1][2],s[2*i+1][3]);
            aH[i][0]=h2u(H0); aH[i][1]=h2u(H1); aH[i][2]=h2u(H2); aH[i][3]=h2u(H3);
            __half2 L0=__floats2half2_rn(s[2*i][0]-__low2float(H0),   s[2*i][1]-__high2float(H0));
            __half2 L1=__floats2half2_rn(s[2*i][2]-__low2float(H1),   s[2*i][3]-__high2float(H1));
            __half2 L2=__floats2half2_rn(s[2*i+1][0]-__low2float(H2), s[2*i+1][1]-__high2float(H2));
            __half2 L3=__floats2half2_rn(s[2*i+1][2]-__low2float(H3), s[2*i+1][3]-__high2float(H3));
            aL[i][0]=h2u(L0); aL[i][1]=h2u(L1); aL[i][2]=h2u(L2); aL[i][3]=h2u(L3);
        }

        // ---- O += P V ----
        const uint32_t vbase = smbV + cur*KSZ + (uint32_t)((lane&7)*KP + (lane>>3)*8)*2;
#pragma unroll
        for (int nt=0;nt<4;nt++){
            uint32_t vh0[4], vh1[4], vl0[4], vl1[4];
            uint32_t a = vbase + (uint32_t)(8*nt*KP)*2;
            ldsm4(vh0, a);       ldsm4(vh1, a + 64);
            ldsm4(vl0, a + (uint32_t)(32*KP)*2); ldsm4(vl1, a + (uint32_t)(32*KP)*2 + 64);
#pragma unroll
            for (int i=0;i<4;i++){
                const uint32_t* bhv = (i<2)? &vh0[2*i] : &vh1[2*(i-2)];
                const uint32_t* blv = (i<2)? &vl0[2*i] : &vl1[2*(i-2)];
                mma16816(Oc[nt], aH[i], bhv);
                mma16816(Oc[nt], aH[i], blv);
                mma16816(Oc[nt], aL[i], bhv);
            }
        }
    }

    l0 += __shfl_xor_sync(0xffffffffu,l0,1);
    l0 += __shfl_xor_sync(0xffffffffu,l0,2);
    l1 += __shfl_xor_sync(0xffffffffu,l1,1);
    l1 += __shfl_xor_sync(0xffffffffu,l1,2);
    float inv0=1.0f/l0, inv1=1.0f/l1;
    float* op = g_AO + ((size_t)(b*NN)+q0+16*w+r0)*DD + h*DKK + 2*cq;
#pragma unroll
    for (int nt=0;nt<4;nt++){
        float2 v0={Oc[nt][0]*inv0, Oc[nt][1]*inv0};
        float2 v1={Oc[nt][2]*inv1, Oc[nt][3]*inv1};
        *(float2*)(op + 8*nt)        = v0;
        *(float2*)(op + 8*nt + 8*DD) = v1;
    }
}

// ---------------------------------------------------------------------------
extern "C" void kernel_launch(void* const* d_in, const int* in_sizes, int n_in,
                              void* d_out, int out_size)
{
    const float* x    = (const float*)d_in[0];
    const float* edge = (const float*)d_in[1];
    const int*   mask = (const int*)  d_in[2];
    const float* wq   = (const float*)d_in[3];
    const float* wk   = (const float*)d_in[4];
    const float* wv   = (const float*)d_in[5];
    const float* wo   = (const float*)d_in[6];
    const float* bo   = (const float*)d_in[7];
    float* out = (float*)d_out;

    dim3 g1((BB*NN)/64, DD/64, 3);
    lin_kernel<<<g1,256>>>(x, wq, wk, wv, nullptr, nullptr, 0);

    dim3 g2(HH, BB*16);
    attn_kernel<<<g2,256>>>(edge, mask);

    dim3 g3((BB*NN)/64, DD/64, 1);
    lin_kernel<<<g3,256>>>(x, wo, nullptr, nullptr, bo, out, 1);
}

// round 8
// speedup vs baseline: 2.2487x; 1.1268x over previous
#include <cuda_runtime.h>
#include <cuda_fp16.h>
#include <mma.h>
#include <cstdint>
using namespace nvcuda;

#define BB  4
#define NN  2048
#define DD  256
#define HH  8
#define DKK 32
#define INV_SCALE 0.17677669529663687f

__device__ __half g_Qs [BB*HH*NN*64];   // [bh][n][hi32|lo32], Q pre-scaled
__device__ __half g_Ks [BB*HH*NN*64];
__device__ __half g_Vth[BB*HH*DKK*NN];  // [bh][dk][n]
__device__ __half g_Vtl[BB*HH*DKK*NN];
__device__ float  g_AO [BB*NN*DD];

// deg-3 exp on FMA pipe: exp(x) = 2^(x*log2e), 2^f minimax on [-0.5,0.5]
__device__ __forceinline__ float fexp(float x){
    x = fmaxf(x, -80.f);
    float t = x * 1.4426950408889634f;
    float y = t + 12582912.f;
    int   n = __float_as_int(y) - 0x4B400000;
    float f = t - (y - 12582912.f);
    float p = fmaf(f, 0.055826318f, 0.24015361f);
    p = fmaf(p, f, 0.69315308f);
    p = fmaf(p, f, 0.99999989f);
    return __int_as_float(__float_as_int(p) + (n << 23));
}

__device__ __forceinline__ void mma16816(float* c, const uint32_t* a, const uint32_t* b){
    asm volatile("mma.sync.aligned.m16n8k16.row.col.f32.f16.f16.f32 "
        "{%0,%1,%2,%3}, {%4,%5,%6,%7}, {%8,%9}, {%0,%1,%2,%3};"
        : "+f"(c[0]), "+f"(c[1]), "+f"(c[2]), "+f"(c[3])
        : "r"(a[0]), "r"(a[1]), "r"(a[2]), "r"(a[3]), "r"(b[0]), "r"(b[1]));
}
__device__ __forceinline__ uint32_t h2u(__half2 v){ return *reinterpret_cast<uint32_t*>(&v); }
__device__ __forceinline__ uint32_t smem_u32(const void* p){
    uint32_t a;
    asm("{ .reg .u64 t; cvta.to.shared.u64 t, %1; cvt.u32.u64 %0, t; }" : "=r"(a) : "l"(p));
    return a;
}
__device__ __forceinline__ void ldsm4(uint32_t* r, uint32_t a){
    asm volatile("ldmatrix.sync.aligned.m8n8.x4.shared.b16 {%0,%1,%2,%3}, [%4];"
        : "=r"(r[0]),"=r"(r[1]),"=r"(r[2]),"=r"(r[3]) : "r"(a));
}
#define CP16(d,s) asm volatile("cp.async.cg.shared.global [%0], [%1], 16;\n"::"r"(d),"l"(s))
#define CPC()     asm volatile("cp.async.commit_group;\n":::"memory")
#define CPW0()    asm volatile("cp.async.wait_group 0;\n":::"memory")

// ---------------- WMMA linear ----------------
#define LDHH 40
#define LDSS 72
typedef wmma::fragment<wmma::matrix_a,16,16,16,__half,wmma::row_major> FragA;
typedef wmma::fragment<wmma::matrix_b,16,16,16,__half,wmma::col_major> FragBc;
typedef wmma::fragment<wmma::accumulator,16,16,16,float> FragC;

__device__ __forceinline__ void load_split(const float* __restrict__ g, int stride,
                                           __half (*H)[LDHH], __half (*L)[LDHH], int t){
    for (int i=t;i<1024;i+=256){
        int r=i>>4, c=(i&15)<<1;
        float2 v=*reinterpret_cast<const float2*>(g+(size_t)r*stride+c);
        __half h0=__float2half_rn(v.x), h1=__float2half_rn(v.y);
        H[r][c]=h0; H[r][c+1]=h1;
        L[r][c]=__float2half_rn(v.x-__half2float(h0));
        L[r][c+1]=__float2half_rn(v.y-__half2float(h1));
    }
}

__global__ __launch_bounds__(256) void lin_kernel(
    const float* __restrict__ src, const float* __restrict__ W0,
    const float* __restrict__ W1,  const float* __restrict__ W2,
    const float* __restrict__ bo,  float* __restrict__ out, int mode)
{
    __shared__ __half Xh[64][LDHH], Xl[64][LDHH], Wh[64][LDHH], Wl[64][LDHH];
    __shared__ float  C[64][LDSS];
    const int z = blockIdx.z;
    const float* A = (mode==1) ? (const float*)g_AO : src;
    const float* W = (mode==1) ? W0 : (z==0?W0:(z==1?W1:W2));
    const int row0=blockIdx.x*64, col0=blockIdx.y*64;
    const int t=threadIdx.x, w=t>>5, rb=w>>1, cb0=(w&1)*2;

    FragC c[2]; wmma::fill_fragment(c[0],0.f); wmma::fill_fragment(c[1],0.f);
    for (int k0=0;k0<DD;k0+=32){
        __syncthreads();
        load_split(A+(size_t)row0*DD+k0, DD, Xh, Xl, t);
        load_split(W+(size_t)col0*DD+k0, DD, Wh, Wl, t);
        __syncthreads();
#pragma unroll
        for (int ks=0;ks<2;ks++){
            FragA ah,al;
            wmma::load_matrix_sync(ah,&Xh[rb*16][ks*16],LDHH);
            wmma::load_matrix_sync(al,&Xl[rb*16][ks*16],LDHH);
#pragma unroll
            for (int q=0;q<2;q++){
                FragBc bh,bl;
                wmma::load_matrix_sync(bh,&Wh[(cb0+q)*16][ks*16],LDHH);
                wmma::load_matrix_sync(bl,&Wl[(cb0+q)*16][ks*16],LDHH);
                wmma::mma_sync(c[q],ah,bh,c[q]);
                wmma::mma_sync(c[q],ah,bl,c[q]);
                wmma::mma_sync(c[q],al,bh,c[q]);
            }
        }
    }
    wmma::store_matrix_sync(&C[rb*16][cb0*16],    c[0],LDSS,wmma::mem_row_major);
    wmma::store_matrix_sync(&C[rb*16][(cb0+1)*16],c[1],LDSS,wmma::mem_row_major);
    __syncthreads();

    if (mode==0){
        if (z<2){
            __half* dst = (z==0) ? g_Qs : g_Ks;
            for (int i=t;i<2048;i+=256){
                int r=i>>5, cp=(i&31)*2;
                int rg=row0+r, b=rg>>11, n=rg&(NN-1);
                int cg=col0+cp, h=cg>>5, dk=cg&31;
                float v0=C[r][cp], v1=C[r][cp+1];
                if (z==0){ v0*=INV_SCALE; v1*=INV_SCALE; }
                __half h0=__float2half_rn(v0), h1=__float2half_rn(v1);
                __half l0=__float2half_rn(v0-__half2float(h0));
                __half l1=__float2half_rn(v1-__half2float(h1));
                size_t base=((size_t)(b*HH+h)*NN+n)*64;
                *reinterpret_cast<__half2*>(dst+base+dk)    = __halves2half2(h0,h1);
                *reinterpret_cast<__half2*>(dst+base+32+dk) = __halves2half2(l0,l1);
            }
        } else {
            for (int i=t;i<2048;i+=256){
                int np=i&31, cc=i>>5;
                int rg=row0+np*2, b=rg>>11, n=rg&(NN-1);
                int cg=col0+cc, h=cg>>5, dk=cg&31;
                float v0=C[np*2][cc], v1=C[np*2+1][cc];
                __half h0=__float2half_rn(v0), h1=__float2half_rn(v1);
                __half l0=__float2half_rn(v0-__half2float(h0));
                __half l1=__float2half_rn(v1-__half2float(h1));
                size_t base=((size_t)(b*HH+h)*DKK+dk)*NN+n;
                *reinterpret_cast<__half2*>(g_Vth+base) = __halves2half2(h0,h1);
                *reinterpret_cast<__half2*>(g_Vtl+base) = __halves2half2(l0,l1);
            }
        }
    } else {
        for (int i=t;i<4096;i+=256){
            int r=i>>6, cc=i&63;
            out[(size_t)(row0+r)*DD+col0+cc] = C[r][cc] + bo[col0+cc];
        }
    }
}

// ---------------- FA2 attention: ldmatrix + cp.async, 2-pass PV ----------------
#define KP  72
#define KSZ (64*KP*2)

__global__ __launch_bounds__(256,2) void attn_kernel(
    const float* __restrict__ edge, const int* __restrict__ mask)
{
    __shared__ __half Ks[2][64][KP];
    __shared__ __half Vs[2][64][KP];   // rows 0-31 V^T hi, 32-63 V^T lo

    const int tid=threadIdx.x, w=tid>>5, lane=tid&31;
    const int h=blockIdx.x, b=blockIdx.y>>4, qt=blockIdx.y&15;
    const int q0=qt*128, bh=b*HH+h;
    const int r0=lane>>2, cq=lane&3;

    const __half* Qg = g_Qs + ((size_t)bh*NN + q0 + 16*w)*64;
    const __half* Kg = g_Ks + (size_t)bh*NN*64;
    const __half* VgH= g_Vth + (size_t)bh*DKK*NN;
    const __half* VgL= g_Vtl + (size_t)bh*DKK*NN;

    const uint32_t smbK = smem_u32(&Ks[0][0][0]);
    const uint32_t smbV = smem_u32(&Vs[0][0][0]);

    uint32_t qh[2][4], ql[2][4];
#pragma unroll
    for (int ks=0;ks<2;ks++){
        int col=16*ks+2*cq;
        qh[ks][0]=*(const uint32_t*)(Qg+(size_t) r0   *64+col);
        qh[ks][1]=*(const uint32_t*)(Qg+(size_t)(r0+8)*64+col);
        qh[ks][2]=*(const uint32_t*)(Qg+(size_t) r0   *64+col+8);
        qh[ks][3]=*(const uint32_t*)(Qg+(size_t)(r0+8)*64+col+8);
        ql[ks][0]=*(const uint32_t*)(Qg+(size_t) r0   *64+32+col);
        ql[ks][1]=*(const uint32_t*)(Qg+(size_t)(r0+8)*64+32+col);
        ql[ks][2]=*(const uint32_t*)(Qg+(size_t) r0   *64+32+col+8);
        ql[ks][3]=*(const uint32_t*)(Qg+(size_t)(r0+8)*64+32+col+8);
    }

    float Oc[4][4];
#pragma unroll
    for (int i=0;i<4;i++){ Oc[i][0]=0.f; Oc[i][1]=0.f; Oc[i][2]=0.f; Oc[i][3]=0.f; }
    float mr0=-1e30f, mr1=-1e30f, l0=0.f, l1=0.f;
    const size_t erow = ((size_t)(b*NN)+q0+16*w+r0)*NN + 2*cq;

    {
        int g0=tid, g1=tid+256;
        int ra=g0>>3, ca=(g0&7)*8, rb_=g1>>3, cb=(g1&7)*8;
        CP16(smbK+(uint32_t)(ra*KP+ca)*2,  Kg+(size_t)ra*64+ca);
        CP16(smbK+(uint32_t)(rb_*KP+cb)*2, Kg+(size_t)rb_*64+cb);
        int p0=g0>>8, v0r=(g0>>3)&31, p1=g1>>8, v1r=(g1>>3)&31;
        CP16(smbV+(uint32_t)((p0*32+v0r)*KP+ca)*2, (p0?VgL:VgH)+(size_t)v0r*NN+ca);
        CP16(smbV+(uint32_t)((p1*32+v1r)*KP+cb)*2, (p1?VgL:VgH)+(size_t)v1r*NN+cb);
        CPC();
    }

#pragma unroll 1
    for (int tt=0;tt<32;tt++){
        const int cur=tt&1, m0=tt*64;
        CPW0();
        __syncthreads();
        if (tt<31){
            const uint32_t kb=smbK+(cur^1)*KSZ, vb=smbV+(cur^1)*KSZ;
            const int m1=m0+64;
            int g0=tid, g1=tid+256;
            int ra=g0>>3, ca=(g0&7)*8, rb_=g1>>3, cb=(g1&7)*8;
            CP16(kb+(uint32_t)(ra*KP+ca)*2,  Kg+(size_t)(m1+ra)*64+ca);
            CP16(kb+(uint32_t)(rb_*KP+cb)*2, Kg+(size_t)(m1+rb_)*64+cb);
            int p0=g0>>8, v0r=(g0>>3)&31, p1=g1>>8, v1r=(g1>>3)&31;
            CP16(vb+(uint32_t)((p0*32+v0r)*KP+ca)*2, (p0?VgL:VgH)+(size_t)v0r*NN+m1+ca);
            CP16(vb+(uint32_t)((p1*32+v1r)*KP+cb)*2, (p1?VgL:VgH)+(size_t)v1r*NN+m1+cb);
            CPC();
        }

        // ---- S = Q K^T ----
        float s[8][4];
#pragma unroll
        for (int j=0;j<8;j++){ s[j][0]=0.f; s[j][1]=0.f; s[j][2]=0.f; s[j][3]=0.f; }
        const uint32_t kbase = smbK + cur*KSZ + (uint32_t)((lane&7)*KP + (lane>>3)*8)*2;
#pragma unroll
        for (int j=0;j<8;j++){
            uint32_t bh4[4], bl4[4];
            uint32_t a = kbase + (uint32_t)(8*j*KP)*2;
            ldsm4(bh4, a);
            ldsm4(bl4, a + 64);
            mma16816(s[j], qh[0], &bh4[0]); mma16816(s[j], qh[1], &bh4[2]);
            mma16816(s[j], qh[0], &bl4[0]); mma16816(s[j], qh[1], &bl4[2]);
            mma16816(s[j], ql[0], &bh4[0]); mma16816(s[j], ql[1], &bh4[2]);
        }

        // ---- edge + mask + online softmax ----
        const float* ep = edge + erow + m0;
        const int*   mp = mask + erow + m0;
        float mt0=-1e30f, mt1=-1e30f;
#pragma unroll
        for (int j=0;j<8;j++){
            float2 e0=*(const float2*)(ep+8*j);
            int2   k0=*(const int2*)  (mp+8*j);
            float2 e1=*(const float2*)(ep+8*j+(size_t)8*NN);
            int2   k1=*(const int2*)  (mp+8*j+(size_t)8*NN);
            s[j][0]=k0.x? s[j][0]+e0.x : -1e9f;
            s[j][1]=k0.y? s[j][1]+e0.y : -1e9f;
            s[j][2]=k1.x? s[j][2]+e1.x : -1e9f;
            s[j][3]=k1.y? s[j][3]+e1.y : -1e9f;
            mt0=fmaxf(mt0,fmaxf(s[j][0],s[j][1]));
            mt1=fmaxf(mt1,fmaxf(s[j][2],s[j][3]));
        }
        mt0=fmaxf(mt0,__shfl_xor_sync(0xffffffffu,mt0,1));
        mt0=fmaxf(mt0,__shfl_xor_sync(0xffffffffu,mt0,2));
        mt1=fmaxf(mt1,__shfl_xor_sync(0xffffffffu,mt1,1));
        mt1=fmaxf(mt1,__shfl_xor_sync(0xffffffffu,mt1,2));
        float mn0=fmaxf(mr0,mt0), mn1=fmaxf(mr1,mt1);
        float c0=fexp(mr0-mn0), c1=fexp(mr1-mn1);
        mr0=mn0; mr1=mn1;
        float ls0=0.f, ls1=0.f;
#pragma unroll
        for (int j=0;j<8;j++){
            s[j][0]=fexp(s[j][0]-mn0); s[j][1]=fexp(s[j][1]-mn0); ls0+=s[j][0]+s[j][1];
            s[j][2]=fexp(s[j][2]-mn1); s[j][3]=fexp(s[j][3]-mn1); ls1+=s[j][2]+s[j][3];
        }
        l0=l0*c0+ls0; l1=l1*c1+ls1;
#pragma unroll
        for (int nt=0;nt<4;nt++){ Oc[nt][0]*=c0; Oc[nt][1]*=c0; Oc[nt][2]*=c1; Oc[nt][3]*=c1; }

        // ---- build P fragments (hi only) ----
        uint32_t aH[4][4];
#pragma unroll
        for (int i=0;i<4;i++){
            aH[i][0]=h2u(__floats2half2_rn(s[2*i][0],  s[2*i][1]));
            aH[i][1]=h2u(__floats2half2_rn(s[2*i][2],  s[2*i][3]));
            aH[i][2]=h2u(__floats2half2_rn(s[2*i+1][0],s[2*i+1][1]));
            aH[i][3]=h2u(__floats2half2_rn(s[2*i+1][2],s[2*i+1][3]));
        }

        // ---- O += P V (P hi x V hi/lo) ----
        const uint32_t vbase = smbV + cur*KSZ + (uint32_t)((lane&7)*KP + (lane>>3)*8)*2;
#pragma unroll
        for (int nt=0;nt<4;nt++){
            uint32_t vh0[4], vh1[4], vl0[4], vl1[4];
            uint32_t a = vbase + (uint32_t)(8*nt*KP)*2;
            ldsm4(vh0, a);       ldsm4(vh1, a + 64);
            ldsm4(vl0, a + (uint32_t)(32*KP)*2); ldsm4(vl1, a + (uint32_t)(32*KP)*2 + 64);
#pragma unroll
            for (int i=0;i<4;i++){
                const uint32_t* bhv = (i<2)? &vh0[2*i] : &vh1[2*(i-2)];
                const uint32_t* blv = (i<2)? &vl0[2*i] : &vl1[2*(i-2)];
                mma16816(Oc[nt], aH[i], bhv);
                mma16816(Oc[nt], aH[i], blv);
            }
        }
    }

    l0 += __shfl_xor_sync(0xffffffffu,l0,1);
    l0 += __shfl_xor_sync(0xffffffffu,l0,2);
    l1 += __shfl_xor_sync(0xffffffffu,l1,1);
    l1 += __shfl_xor_sync(0xffffffffu,l1,2);
    float inv0=1.0f/l0, inv1=1.0f/l1;
    float* op = g_AO + ((size_t)(b*NN)+q0+16*w+r0)*DD + h*DKK + 2*cq;
#pragma unroll
    for (int nt=0;nt<4;nt++){
        float2 v0={Oc[nt][0]*inv0, Oc[nt][1]*inv0};
        float2 v1={Oc[nt][2]*inv1, Oc[nt][3]*inv1};
        *(float2*)(op + 8*nt)        = v0;
        *(float2*)(op + 8*nt + 8*DD) = v1;
    }
}

// ---------------------------------------------------------------------------
extern "C" void kernel_launch(void* const* d_in, const int* in_sizes, int n_in,
                              void* d_out, int out_size)
{
    const float* x    = (const float*)d_in[0];
    const float* edge = (const float*)d_in[1];
    const int*   mask = (const int*)  d_in[2];
    const float* wq   = (const float*)d_in[3];
    const float* wk   = (const float*)d_in[4];
    const float* wv   = (const float*)d_in[5];
    const float* wo   = (const float*)d_in[6];
    const float* bo   = (const float*)d_in[7];
    float* out = (float*)d_out;

    dim3 g1((BB*NN)/64, DD/64, 3);
    lin_kernel<<<g1,256>>>(x, wq, wk, wv, nullptr, nullptr, 0);

    dim3 g2(HH, BB*16);
    attn_kernel<<<g2,256>>>(edge, mask);

    dim3 g3((BB*NN)/64, DD/64, 1);
    lin_kernel<<<g3,256>>>(x, wo, nullptr, nullptr, bo, out, 1);
}